// round 1
// baseline (speedup 1.0000x reference)
#include <cuda_runtime.h>

#define HID 128
#define EDIM 64
#define NN 50000
#define NE 800000

// Scratch (device globals: allocation-free rule)
__device__ float g_h[(size_t)NN * HID];    // node embeddings  [NN,128]
__device__ float g_agg[(size_t)NN * HID];  // segment-sum accumulator [NN,128]

// ---------------------------------------------------------------------------
// Block-level GEMM tile: 64 rows x 128 cols output, K-chunk of 64.
// 256 threads: ct = tid&15 -> cols ct*8..ct*8+7 ; rt = tid>>4 -> rows rt*4..rt*4+3
// sA: [64][lda] (lda chosen so 4-row stride lands on distinct banks)
// sW: [64][128] row-major in smem
// ---------------------------------------------------------------------------
__device__ __forceinline__ void mm_k64(const float* __restrict__ sA, int lda,
                                       const float* __restrict__ sW,
                                       float acc[4][8], int rt, int ct) {
    const float* pa0 = sA + (rt * 4 + 0) * lda;
    const float* pa1 = sA + (rt * 4 + 1) * lda;
    const float* pa2 = sA + (rt * 4 + 2) * lda;
    const float* pa3 = sA + (rt * 4 + 3) * lda;
    const float* pw  = sW + ct * 8;
#pragma unroll 8
    for (int k = 0; k < 64; ++k) {
        float a0 = pa0[k], a1 = pa1[k], a2 = pa2[k], a3 = pa3[k];
        float4 w0 = *reinterpret_cast<const float4*>(pw + k * HID);
        float4 w1 = *reinterpret_cast<const float4*>(pw + k * HID + 4);
        float w[8] = {w0.x, w0.y, w0.z, w0.w, w1.x, w1.y, w1.z, w1.w};
        float a[4] = {a0, a1, a2, a3};
#pragma unroll
        for (int i = 0; i < 4; ++i)
#pragma unroll
            for (int j = 0; j < 8; ++j)
                acc[i][j] = fmaf(a[i], w[j], acc[i][j]);
    }
}

// Cooperative load of a [64][128] fp32 weight tile into smem (coalesced float4)
__device__ __forceinline__ void load_w64(float* sW, const float* __restrict__ gW,
                                         int tid) {
#pragma unroll
    for (int i = tid; i < 64 * HID / 4; i += 256)
        reinterpret_cast<float4*>(sW)[i] = reinterpret_cast<const float4*>(gW)[i];
}

__device__ __forceinline__ void zero_acc(float acc[4][8]) {
#pragma unroll
    for (int i = 0; i < 4; ++i)
#pragma unroll
        for (int j = 0; j < 8; ++j) acc[i][j] = 0.f;
}

// ---------------------------------------------------------------------------
// Kernel 1: h = node_feats @ node_W + node_b   -> g_h
// ---------------------------------------------------------------------------
__global__ __launch_bounds__(256) void k_node_embed(const float* __restrict__ nf,
                                                    const float* __restrict__ W,
                                                    const float* __restrict__ b) {
    extern __shared__ float smem[];
    float* sA = smem;            // 64 x 132
    float* sW = sA + 64 * 132;   // 64 x 128
    const int tid = threadIdx.x;
    const int ct = tid & 15, rt = tid >> 4;
    const int base = blockIdx.x * 64;

    for (int i = tid; i < 64 * 32; i += 256) {
        int r = i >> 5, c4 = (i & 31) * 4;
        float4 v = make_float4(0.f, 0.f, 0.f, 0.f);
        int gr = base + r;
        if (gr < NN) v = *reinterpret_cast<const float4*>(nf + (size_t)gr * HID + c4);
        *reinterpret_cast<float4*>(sA + r * 132 + c4) = v;
    }

    float acc[4][8];
    zero_acc(acc);
#pragma unroll
    for (int kt = 0; kt < 2; ++kt) {
        __syncthreads();
        load_w64(sW, W + kt * 64 * HID, tid);
        __syncthreads();
        mm_k64(sA + kt * 64, 132, sW, acc, rt, ct);
    }

    const float4 b0 = *reinterpret_cast<const float4*>(b + ct * 8);
    const float4 b1 = *reinterpret_cast<const float4*>(b + ct * 8 + 4);
    const float bias[8] = {b0.x, b0.y, b0.z, b0.w, b1.x, b1.y, b1.z, b1.w};
#pragma unroll
    for (int i = 0; i < 4; ++i) {
        int gr = base + rt * 4 + i;
        if (gr < NN) {
            float4 o0 = make_float4(acc[i][0] + bias[0], acc[i][1] + bias[1],
                                    acc[i][2] + bias[2], acc[i][3] + bias[3]);
            float4 o1 = make_float4(acc[i][4] + bias[4], acc[i][5] + bias[5],
                                    acc[i][6] + bias[6], acc[i][7] + bias[7]);
            *reinterpret_cast<float4*>(g_h + (size_t)gr * HID + ct * 8) = o0;
            *reinterpret_cast<float4*>(g_h + (size_t)gr * HID + ct * 8 + 4) = o1;
        }
    }
}

// ---------------------------------------------------------------------------
// Kernel 2: zero the aggregation buffer
// ---------------------------------------------------------------------------
__global__ __launch_bounds__(256) void k_zero_agg() {
    size_t i = (size_t)blockIdx.x * 256 + threadIdx.x;  // float4 index
    reinterpret_cast<float4*>(g_agg)[i] = make_float4(0.f, 0.f, 0.f, 0.f);
}

// ---------------------------------------------------------------------------
// Kernel 3: fused edge pipeline per 64-edge tile:
//   e = ef@eW+eb ; msg_in=[h[src]|e] ; t=relu(msg_in@W1+b1) ; m=t@W2+b2
//   atomicAdd m into g_agg[dst]
// ---------------------------------------------------------------------------
__global__ __launch_bounds__(256) void k_edge(const int* __restrict__ eidx,
                                              const float* __restrict__ ef,
                                              const float* __restrict__ eW,
                                              const float* __restrict__ eb,
                                              const float* __restrict__ W1,
                                              const float* __restrict__ b1,
                                              const float* __restrict__ W2,
                                              const float* __restrict__ b2) {
    extern __shared__ float smem[];
    float* sMsg = smem;                 // 64 x 260  (cols 0..127 = h[src], 128..255 = e)
    float* sW   = sMsg + 64 * 260;      // 64 x 128  weight staging
    float* sT   = sW + 64 * 128;        // 64 x 132  edge_feats, then t
    int* sSrc = reinterpret_cast<int*>(sT + 64 * 132);
    int* sDst = sSrc + 64;

    const int tid = threadIdx.x;
    const int ct = tid & 15, rt = tid >> 4;
    const int e0 = blockIdx.x * 64;

    if (tid < 64) {
        sSrc[tid] = eidx[e0 + tid];
        sDst[tid] = eidx[NE + e0 + tid];
    }
    // edge_feats tile [64,64] -> sT
    for (int i = tid; i < 64 * 16; i += 256) {
        int r = i >> 4, c4 = (i & 15) * 4;
        *reinterpret_cast<float4*>(sT + r * 132 + c4) =
            *reinterpret_cast<const float4*>(ef + (size_t)(e0 + r) * EDIM + c4);
    }
    __syncthreads();  // sSrc visible

    // gather h[src] -> sMsg[:,0:128)  (L2-resident)
    for (int i = tid; i < 64 * 32; i += 256) {
        int r = i >> 5, c4 = (i & 31) * 4;
        *reinterpret_cast<float4*>(sMsg + r * 260 + c4) =
            *reinterpret_cast<const float4*>(g_h + (size_t)sSrc[r] * HID + c4);
    }
    load_w64(sW, eW, tid);
    __syncthreads();  // sT, sW, gather complete

    float acc[4][8];
    zero_acc(acc);
    mm_k64(sT, 132, sW, acc, rt, ct);  // e = ef @ eW  (K=64)

    {  // e + eb -> sMsg[:,128:256)
        const float4 eb0 = *reinterpret_cast<const float4*>(eb + ct * 8);
        const float4 eb1 = *reinterpret_cast<const float4*>(eb + ct * 8 + 4);
#pragma unroll
        for (int i = 0; i < 4; ++i) {
            float* p = sMsg + (rt * 4 + i) * 260 + 128 + ct * 8;
            float4 o0 = make_float4(acc[i][0] + eb0.x, acc[i][1] + eb0.y,
                                    acc[i][2] + eb0.z, acc[i][3] + eb0.w);
            float4 o1 = make_float4(acc[i][4] + eb1.x, acc[i][5] + eb1.y,
                                    acc[i][6] + eb1.z, acc[i][7] + eb1.w);
            *reinterpret_cast<float4*>(p) = o0;
            *reinterpret_cast<float4*>(p + 4) = o1;
        }
    }
    __syncthreads();  // sMsg complete; sW reads done

    // t = relu(msg_in @ W1 + b1)   K = 256
    zero_acc(acc);
#pragma unroll
    for (int kt = 0; kt < 4; ++kt) {
        load_w64(sW, W1 + (size_t)kt * 64 * HID, tid);
        __syncthreads();
        mm_k64(sMsg + kt * 64, 260, sW, acc, rt, ct);
        __syncthreads();
    }
    {
        const float4 bb0 = *reinterpret_cast<const float4*>(b1 + ct * 8);
        const float4 bb1 = *reinterpret_cast<const float4*>(b1 + ct * 8 + 4);
        const float bb[8] = {bb0.x, bb0.y, bb0.z, bb0.w, bb1.x, bb1.y, bb1.z, bb1.w};
#pragma unroll
        for (int i = 0; i < 4; ++i) {
            float* p = sT + (rt * 4 + i) * 132 + ct * 8;
            float4 o0 = make_float4(fmaxf(acc[i][0] + bb[0], 0.f), fmaxf(acc[i][1] + bb[1], 0.f),
                                    fmaxf(acc[i][2] + bb[2], 0.f), fmaxf(acc[i][3] + bb[3], 0.f));
            float4 o1 = make_float4(fmaxf(acc[i][4] + bb[4], 0.f), fmaxf(acc[i][5] + bb[5], 0.f),
                                    fmaxf(acc[i][6] + bb[6], 0.f), fmaxf(acc[i][7] + bb[7], 0.f));
            *reinterpret_cast<float4*>(p) = o0;
            *reinterpret_cast<float4*>(p + 4) = o1;
        }
    }

    // m = t @ W2 + b2   K = 128
    zero_acc(acc);
#pragma unroll
    for (int kt = 0; kt < 2; ++kt) {
        load_w64(sW, W2 + (size_t)kt * 64 * HID, tid);
        __syncthreads();  // also orders sT writes before reads (kt=0)
        mm_k64(sT + kt * 64, 132, sW, acc, rt, ct);
        __syncthreads();
    }

    {  // scatter-add into g_agg[dst]
        const float4 mb0 = *reinterpret_cast<const float4*>(b2 + ct * 8);
        const float4 mb1 = *reinterpret_cast<const float4*>(b2 + ct * 8 + 4);
        const float mb[8] = {mb0.x, mb0.y, mb0.z, mb0.w, mb1.x, mb1.y, mb1.z, mb1.w};
#pragma unroll
        for (int i = 0; i < 4; ++i) {
            int d = sDst[rt * 4 + i];
            float* p = g_agg + (size_t)d * HID + ct * 8;
#pragma unroll
            for (int j = 0; j < 8; ++j) atomicAdd(p + j, acc[i][j] + mb[j]);
        }
    }
}

// ---------------------------------------------------------------------------
// Kernel 4: out = relu([nf|agg] @ U1 + ub1) @ U2 + ub2
// ---------------------------------------------------------------------------
__global__ __launch_bounds__(256) void k_update(const float* __restrict__ nf,
                                                const float* __restrict__ W1,
                                                const float* __restrict__ b1,
                                                const float* __restrict__ W2,
                                                const float* __restrict__ b2,
                                                float* __restrict__ out) {
    extern __shared__ float smem[];
    float* sMsg = smem;             // 64 x 260
    float* sW   = sMsg + 64 * 260;  // 64 x 128
    float* sT   = sW + 64 * 128;    // 64 x 132

    const int tid = threadIdx.x;
    const int ct = tid & 15, rt = tid >> 4;
    const int base = blockIdx.x * 64;

    // [nf | agg] -> sMsg
    for (int i = tid; i < 64 * 32; i += 256) {
        int r = i >> 5, c4 = (i & 31) * 4;
        int gr = base + r;
        float4 v0 = make_float4(0.f, 0.f, 0.f, 0.f), v1 = v0;
        if (gr < NN) {
            v0 = *reinterpret_cast<const float4*>(nf + (size_t)gr * HID + c4);
            v1 = *reinterpret_cast<const float4*>(g_agg + (size_t)gr * HID + c4);
        }
        *reinterpret_cast<float4*>(sMsg + r * 260 + c4) = v0;
        *reinterpret_cast<float4*>(sMsg + r * 260 + 128 + c4) = v1;
    }

    float acc[4][8];
    zero_acc(acc);
#pragma unroll
    for (int kt = 0; kt < 4; ++kt) {
        __syncthreads();
        load_w64(sW, W1 + (size_t)kt * 64 * HID, tid);
        __syncthreads();
        mm_k64(sMsg + kt * 64, 260, sW, acc, rt, ct);
    }
    __syncthreads();
    {
        const float4 bb0 = *reinterpret_cast<const float4*>(b1 + ct * 8);
        const float4 bb1 = *reinterpret_cast<const float4*>(b1 + ct * 8 + 4);
        const float bb[8] = {bb0.x, bb0.y, bb0.z, bb0.w, bb1.x, bb1.y, bb1.z, bb1.w};
#pragma unroll
        for (int i = 0; i < 4; ++i) {
            float* p = sT + (rt * 4 + i) * 132 + ct * 8;
            float4 o0 = make_float4(fmaxf(acc[i][0] + bb[0], 0.f), fmaxf(acc[i][1] + bb[1], 0.f),
                                    fmaxf(acc[i][2] + bb[2], 0.f), fmaxf(acc[i][3] + bb[3], 0.f));
            float4 o1 = make_float4(fmaxf(acc[i][4] + bb[4], 0.f), fmaxf(acc[i][5] + bb[5], 0.f),
                                    fmaxf(acc[i][6] + bb[6], 0.f), fmaxf(acc[i][7] + bb[7], 0.f));
            *reinterpret_cast<float4*>(p) = o0;
            *reinterpret_cast<float4*>(p + 4) = o1;
        }
    }

    zero_acc(acc);
#pragma unroll
    for (int kt = 0; kt < 2; ++kt) {
        load_w64(sW, W2 + (size_t)kt * 64 * HID, tid);
        __syncthreads();
        mm_k64(sT + kt * 64, 132, sW, acc, rt, ct);
        __syncthreads();
    }

    {
        const float4 mb0 = *reinterpret_cast<const float4*>(b2 + ct * 8);
        const float4 mb1 = *reinterpret_cast<const float4*>(b2 + ct * 8 + 4);
        const float mb[8] = {mb0.x, mb0.y, mb0.z, mb0.w, mb1.x, mb1.y, mb1.z, mb1.w};
#pragma unroll
        for (int i = 0; i < 4; ++i) {
            int gr = base + rt * 4 + i;
            if (gr < NN) {
                float* p = out + (size_t)gr * HID + ct * 8;
                float4 o0 = make_float4(acc[i][0] + mb[0], acc[i][1] + mb[1],
                                        acc[i][2] + mb[2], acc[i][3] + mb[3]);
                float4 o1 = make_float4(acc[i][4] + mb[4], acc[i][5] + mb[5],
                                        acc[i][6] + mb[6], acc[i][7] + mb[7]);
                *reinterpret_cast<float4*>(p) = o0;
                *reinterpret_cast<float4*>(p + 4) = o1;
            }
        }
    }
}

// ---------------------------------------------------------------------------
extern "C" void kernel_launch(void* const* d_in, const int* in_sizes, int n_in,
                              void* d_out, int out_size) {
    const float* node_feats = (const float*)d_in[0];
    const int*   edge_idx   = (const int*)d_in[1];
    const float* edge_feats = (const float*)d_in[2];
    const float* node_W     = (const float*)d_in[3];
    const float* node_b     = (const float*)d_in[4];
    const float* edge_W     = (const float*)d_in[5];
    const float* edge_b     = (const float*)d_in[6];
    const float* msg_W1     = (const float*)d_in[7];
    const float* msg_b1     = (const float*)d_in[8];
    const float* msg_W2     = (const float*)d_in[9];
    const float* msg_b2     = (const float*)d_in[10];
    const float* upd_W1     = (const float*)d_in[11];
    const float* upd_b1     = (const float*)d_in[12];
    const float* upd_W2     = (const float*)d_in[13];
    const float* upd_b2     = (const float*)d_in[14];
    float* out = (float*)d_out;

    const int SMEM_NODE = (64 * 132 + 64 * 128) * 4;                       // 66560
    const int SMEM_EDGE = (64 * 260 + 64 * 128 + 64 * 132) * 4 + 128 * 4;  // 133632
    const int SMEM_UPD  = (64 * 260 + 64 * 128 + 64 * 132) * 4;            // 133120

    cudaFuncSetAttribute(k_node_embed, cudaFuncAttributeMaxDynamicSharedMemorySize, SMEM_NODE);
    cudaFuncSetAttribute(k_edge,       cudaFuncAttributeMaxDynamicSharedMemorySize, SMEM_EDGE);
    cudaFuncSetAttribute(k_update,     cudaFuncAttributeMaxDynamicSharedMemorySize, SMEM_UPD);

    const int NB_NODE = (NN + 63) / 64;  // 782
    const int NB_EDGE = NE / 64;         // 12500

    k_zero_agg<<<NN * HID / 4 / 256, 256>>>();  // 6250 blocks
    k_node_embed<<<NB_NODE, 256, SMEM_NODE>>>(node_feats, node_W, node_b);
    k_edge<<<NB_EDGE, 256, SMEM_EDGE>>>(edge_idx, edge_feats, edge_W, edge_b,
                                        msg_W1, msg_b1, msg_W2, msg_b2);
    k_update<<<NB_NODE, 256, SMEM_UPD>>>(node_feats, upd_W1, upd_b1,
                                         upd_W2, upd_b2, out);
}

// round 4
// speedup vs baseline: 2.7784x; 2.7784x over previous
#include <cuda_runtime.h>
#include <cstdint>

#define HID 128
#define NN 50000
#define NE 800000
#define LDA 132   // floats per smem row (528B: bank-rotating, ldmatrix conflict-free)

extern __shared__ char dyn_smem[];

// ---------------- device scratch (allocation-free rule) ----------------
__device__ float g_h[(size_t)NN * HID];    // node embeddings (tf32-truncated)
__device__ float g_agg[(size_t)NN * HID];  // segment-sum accumulator (fp32)
__device__ float g_nWt[128 * 128];         // node_W^T  [N][K] tf32
__device__ float g_eWt[128 * 64];          // edge_W^T  tf32
__device__ float g_W1t[128 * 256];         // msg_W1^T  tf32
__device__ float g_W2t[128 * 128];         // msg_W2^T  tf32
__device__ float g_U1t[128 * 256];         // upd_W1^T  tf32
__device__ float g_U2t[128 * 128];         // upd_W2^T  tf32

// ======================= warp-MMA helpers (generic PTX) =================
__device__ __forceinline__ uint32_t smem_u32(const void* p) {
    uint32_t a;
    asm("{ .reg .u64 t; cvta.to.shared.u64 t, %1; cvt.u32.u64 %0, t; }"
        : "=r"(a) : "l"(p));
    return a;
}
__device__ __forceinline__ uint32_t f2tf(float f) {
    uint32_t u;
    asm("cvt.rna.tf32.f32 %0, %1;" : "=r"(u) : "f"(f));
    return u;
}
__device__ __forceinline__ void ldsm4(uint32_t r[4], uint32_t addr) {
    asm volatile("ldmatrix.sync.aligned.m8n8.x4.shared.b16 {%0,%1,%2,%3}, [%4];"
                 : "=r"(r[0]), "=r"(r[1]), "=r"(r[2]), "=r"(r[3]) : "r"(addr));
}
__device__ __forceinline__ void mma8(float c[4], const uint32_t a[4],
                                     uint32_t b0, uint32_t b1) {
    asm volatile("mma.sync.aligned.m16n8k8.row.col.f32.tf32.tf32.f32 "
                 "{%0,%1,%2,%3}, {%4,%5,%6,%7}, {%8,%9}, {%0,%1,%2,%3};"
                 : "+f"(c[0]), "+f"(c[1]), "+f"(c[2]), "+f"(c[3])
                 : "r"(a[0]), "r"(a[1]), "r"(a[2]), "r"(a[3]), "r"(b0), "r"(b1));
}
__device__ __forceinline__ void zacc(float acc[2][8][4]) {
#pragma unroll
    for (int i = 0; i < 2; ++i)
#pragma unroll
        for (int j = 0; j < 8; ++j)
#pragma unroll
            for (int k = 0; k < 4; ++k) acc[i][j][k] = 0.f;
}

// Warp GEMM: 32x64 output tile, KSTEPS k-steps of 8.
template <int KSTEPS>
__device__ __forceinline__ void wgemm(uint32_t aA0, uint32_t aA1,
                                      const uint32_t bA[4], float acc[2][8][4]) {
#pragma unroll
    for (int ks = 0; ks < KSTEPS; ++ks) {
        uint32_t a0[4], a1[4];
        ldsm4(a0, aA0 + ks * 32);
        ldsm4(a1, aA1 + ks * 32);
#pragma unroll
        for (int jj = 0; jj < 4; ++jj) {
            uint32_t b[4];
            ldsm4(b, bA[jj] + ks * 32);
            mma8(acc[0][2 * jj],     a0, b[0], b[1]);
            mma8(acc[0][2 * jj + 1], a0, b[2], b[3]);
            mma8(acc[1][2 * jj],     a1, b[0], b[1]);
            mma8(acc[1][2 * jj + 1], a1, b[2], b[3]);
        }
    }
}

// Per-lane ldmatrix address offsets (bytes) within a [128][LDA] smem tile.
__device__ __forceinline__ uint32_t a_lane_off(int lane) {
    int row = (lane & 7) + ((lane & 8) ? 8 : 0);
    return (uint32_t)row * (LDA * 4) + ((lane & 16) ? 16 : 0);
}
__device__ __forceinline__ uint32_t b_lane_off(int lane) {
    int row = (lane & 7) + ((lane & 16) ? 8 : 0);
    return (uint32_t)row * (LDA * 4) + ((lane & 8) ? 16 : 0);
}

// ---------------------------------------------------------------------------
// Prep: transpose + tf32-truncate all weight matrices
// ---------------------------------------------------------------------------
__global__ void k_tW(const float* __restrict__ nW, const float* __restrict__ eW,
                     const float* __restrict__ W1, const float* __restrict__ W2,
                     const float* __restrict__ U1, const float* __restrict__ U2) {
    int t = blockIdx.x * blockDim.x + threadIdx.x;
    int tot = gridDim.x * blockDim.x;
    for (int i = t; i < 128 * 128; i += tot) {
        int n = i >> 7, k = i & 127;
        g_nWt[i] = __uint_as_float(f2tf(nW[k * 128 + n]));
        g_W2t[i] = __uint_as_float(f2tf(W2[k * 128 + n]));
        g_U2t[i] = __uint_as_float(f2tf(U2[k * 128 + n]));
    }
    for (int i = t; i < 128 * 64; i += tot) {
        int n = i >> 6, k = i & 63;
        g_eWt[i] = __uint_as_float(f2tf(eW[k * 128 + n]));
    }
    for (int i = t; i < 128 * 256; i += tot) {
        int n = i >> 8, k = i & 255;
        g_W1t[i] = __uint_as_float(f2tf(W1[k * 128 + n]));
        g_U1t[i] = __uint_as_float(f2tf(U1[k * 128 + n]));
    }
}

__global__ __launch_bounds__(256) void k_zero_agg() {
    size_t i = (size_t)blockIdx.x * 256 + threadIdx.x;
    reinterpret_cast<float4*>(g_agg)[i] = make_float4(0.f, 0.f, 0.f, 0.f);
}

// ---------------------------------------------------------------------------
// Kernel 1: h = tf32(node_feats @ node_W + node_b) -> g_h   (128 rows/block)
// ---------------------------------------------------------------------------
__global__ __launch_bounds__(256, 1) void k_node(const float* __restrict__ nf,
                                                 const float* __restrict__ b) {
    float* fsm = reinterpret_cast<float*>(dyn_smem);
    float* sA = fsm;
    float* sB = fsm + 128 * LDA;
    float* sBias = fsm + 2 * 128 * LDA;
    const uint32_t sb0 = smem_u32(dyn_smem);
    const int tid = threadIdx.x, lane = tid & 31, w = tid >> 5;
    const int base = blockIdx.x * 128;

    if (tid < 128) sBias[tid] = b[tid];
    for (int i = tid; i < 128 * 32; i += 256) {
        int r = i >> 5, c = (i & 31) * 4;
        int gr = base + r;
        uint4 u = make_uint4(0, 0, 0, 0);
        if (gr < NN) {
            float4 v = *reinterpret_cast<const float4*>(nf + (size_t)gr * HID + c);
            u = make_uint4(f2tf(v.x), f2tf(v.y), f2tf(v.z), f2tf(v.w));
        }
        *reinterpret_cast<uint4*>(sA + r * LDA + c) = u;
    }
    for (int i = tid; i < 128 * 32; i += 256) {
        int r = i >> 5, c = (i & 31) * 4;
        *reinterpret_cast<float4*>(sB + r * LDA + c) =
            *reinterpret_cast<const float4*>(g_nWt + (size_t)r * 128 + c);
    }
    __syncthreads();

    const int mb = (w & 3) * 32, nb = (w >> 2) * 64;
    uint32_t aA0 = sb0 + (uint32_t)mb * (LDA * 4) + a_lane_off(lane);
    uint32_t aA1 = aA0 + 16 * LDA * 4;
    uint32_t bA[4];
#pragma unroll
    for (int jj = 0; jj < 4; ++jj)
        bA[jj] = sb0 + 128 * LDA * 4 + (uint32_t)(nb + jj * 16) * (LDA * 4) + b_lane_off(lane);

    float acc[2][8][4];
    zacc(acc);
    wgemm<16>(aA0, aA1, bA, acc);

    const int g = lane >> 2, tg = lane & 3;
#pragma unroll
    for (int i = 0; i < 2; ++i) {
        int r0 = base + mb + i * 16 + g;
#pragma unroll
        for (int j = 0; j < 8; ++j) {
            int c = nb + j * 8 + 2 * tg;
            if (r0 < NN) {
                g_h[(size_t)r0 * HID + c] = __uint_as_float(f2tf(acc[i][j][0] + sBias[c]));
                g_h[(size_t)r0 * HID + c + 1] = __uint_as_float(f2tf(acc[i][j][1] + sBias[c + 1]));
            }
            if (r0 + 8 < NN) {
                g_h[(size_t)(r0 + 8) * HID + c] = __uint_as_float(f2tf(acc[i][j][2] + sBias[c]));
                g_h[(size_t)(r0 + 8) * HID + c + 1] = __uint_as_float(f2tf(acc[i][j][3] + sBias[c + 1]));
            }
        }
    }
}

// ---------------------------------------------------------------------------
// Kernel 2: fused edge pipeline (128 edges/block), tf32 warp-MMA
// ---------------------------------------------------------------------------
static constexpr int EDGE_SMEM =
    (3 * 128 * LDA + 3 * 128) * 4 + 2 * 128 * 4;  // 3 tiles + 3 bias + src/dst

__global__ __launch_bounds__(256, 1) void k_edge(const int* __restrict__ eidx,
                                                 const float* __restrict__ ef,
                                                 const float* __restrict__ eb,
                                                 const float* __restrict__ b1,
                                                 const float* __restrict__ b2) {
    float* fsm = reinterpret_cast<float*>(dyn_smem);
    float* sH = fsm;
    float* sE = fsm + 128 * LDA;
    float* sB = fsm + 2 * 128 * LDA;
    float* sEB = fsm + 3 * 128 * LDA;
    float* sB1 = sEB + 128;
    float* sB2 = sB1 + 128;
    int* sSrc = reinterpret_cast<int*>(sB2 + 128);
    int* sDst = sSrc + 128;
    const uint32_t sb0 = smem_u32(dyn_smem);

    const int tid = threadIdx.x, lane = tid & 31, w = tid >> 5;
    const int e0 = blockIdx.x * 128;

    if (tid < 128) {
        sSrc[tid] = eidx[e0 + tid];
        sDst[tid] = eidx[NE + e0 + tid];
        sEB[tid] = eb[tid];
        sB1[tid] = b1[tid];
        sB2[tid] = b2[tid];
    }
    // ef [128x64] cvt -> sE cols 0..63
    for (int i = tid; i < 128 * 16; i += 256) {
        int r = i >> 4, c = (i & 15) * 4;
        float4 v = *reinterpret_cast<const float4*>(ef + (size_t)(e0 + r) * 64 + c);
        *reinterpret_cast<uint4*>(sE + r * LDA + c) =
            make_uint4(f2tf(v.x), f2tf(v.y), f2tf(v.z), f2tf(v.w));
    }
    // eWt [128x64] copy -> sB
    for (int i = tid; i < 128 * 16; i += 256) {
        int r = i >> 4, c = (i & 15) * 4;
        *reinterpret_cast<float4*>(sB + r * LDA + c) =
            *reinterpret_cast<const float4*>(g_eWt + (size_t)r * 64 + c);
    }
    __syncthreads();  // sSrc visible
    // gather h[src] (already tf32) -> sH
    for (int i = tid; i < 128 * 32; i += 256) {
        int r = i >> 5, c = (i & 31) * 4;
        *reinterpret_cast<float4*>(sH + r * LDA + c) =
            *reinterpret_cast<const float4*>(g_h + (size_t)sSrc[r] * HID + c);
    }
    __syncthreads();

    const int mb = (w & 3) * 32, nb = (w >> 2) * 64;
    uint32_t aH0 = sb0 + (uint32_t)mb * (LDA * 4) + a_lane_off(lane);
    uint32_t aH1 = aH0 + 16 * LDA * 4;
    uint32_t aE0 = aH0 + 128 * LDA * 4;
    uint32_t aE1 = aE0 + 16 * LDA * 4;
    uint32_t bA[4];
#pragma unroll
    for (int jj = 0; jj < 4; ++jj)
        bA[jj] = sb0 + 2 * 128 * LDA * 4 + (uint32_t)(nb + jj * 16) * (LDA * 4) + b_lane_off(lane);

    const int g = lane >> 2, tg = lane & 3;
    float acc[2][8][4];

    // ---- GEMM0: e = ef @ eWt^T  (K=64) ----
    zacc(acc);
    wgemm<8>(aE0, aE1, bA, acc);
    __syncthreads();
    // stage W1 ch0 -> sB ; epilogue e -> sE
    for (int i = tid; i < 128 * 32; i += 256) {
        int r = i >> 5, c = (i & 31) * 4;
        *reinterpret_cast<float4*>(sB + r * LDA + c) =
            *reinterpret_cast<const float4*>(g_W1t + (size_t)r * 256 + c);
    }
#pragma unroll
    for (int i = 0; i < 2; ++i) {
        int r0 = mb + i * 16 + g;
#pragma unroll
        for (int j = 0; j < 8; ++j) {
            int c = nb + j * 8 + 2 * tg;
            float2 lo = make_float2(__uint_as_float(f2tf(acc[i][j][0] + sEB[c])),
                                    __uint_as_float(f2tf(acc[i][j][1] + sEB[c + 1])));
            float2 hi = make_float2(__uint_as_float(f2tf(acc[i][j][2] + sEB[c])),
                                    __uint_as_float(f2tf(acc[i][j][3] + sEB[c + 1])));
            *reinterpret_cast<float2*>(sE + r0 * LDA + c) = lo;
            *reinterpret_cast<float2*>(sE + (r0 + 8) * LDA + c) = hi;
        }
    }
    __syncthreads();

    // ---- GEMM1: t = relu([h|e] @ W1t^T + b1)  (K=256 in 2 chunks) ----
    zacc(acc);
    wgemm<16>(aH0, aH1, bA, acc);  // chunk0: A = h
    __syncthreads();
    for (int i = tid; i < 128 * 32; i += 256) {
        int r = i >> 5, c = (i & 31) * 4;
        *reinterpret_cast<float4*>(sB + r * LDA + c) =
            *reinterpret_cast<const float4*>(g_W1t + (size_t)r * 256 + 128 + c);
    }
    __syncthreads();
    wgemm<16>(aE0, aE1, bA, acc);  // chunk1: A = e
    __syncthreads();
    // stage W2 -> sB ; epilogue t = relu(acc+b1) -> sH
    for (int i = tid; i < 128 * 32; i += 256) {
        int r = i >> 5, c = (i & 31) * 4;
        *reinterpret_cast<float4*>(sB + r * LDA + c) =
            *reinterpret_cast<const float4*>(g_W2t + (size_t)r * 128 + c);
    }
#pragma unroll
    for (int i = 0; i < 2; ++i) {
        int r0 = mb + i * 16 + g;
#pragma unroll
        for (int j = 0; j < 8; ++j) {
            int c = nb + j * 8 + 2 * tg;
            float2 lo = make_float2(
                __uint_as_float(f2tf(fmaxf(acc[i][j][0] + sB1[c], 0.f))),
                __uint_as_float(f2tf(fmaxf(acc[i][j][1] + sB1[c + 1], 0.f))));
            float2 hi = make_float2(
                __uint_as_float(f2tf(fmaxf(acc[i][j][2] + sB1[c], 0.f))),
                __uint_as_float(f2tf(fmaxf(acc[i][j][3] + sB1[c + 1], 0.f))));
            *reinterpret_cast<float2*>(sH + r0 * LDA + c) = lo;
            *reinterpret_cast<float2*>(sH + (r0 + 8) * LDA + c) = hi;
        }
    }
    __syncthreads();

    // ---- GEMM2: m = t @ W2t^T + b2  (K=128) -> scatter-add ----
    zacc(acc);
    wgemm<16>(aH0, aH1, bA, acc);
#pragma unroll
    for (int i = 0; i < 2; ++i) {
        int r0 = mb + i * 16 + g;
        float* p0 = g_agg + (size_t)sDst[r0] * HID;
        float* p1 = g_agg + (size_t)sDst[r0 + 8] * HID;
#pragma unroll
        for (int j = 0; j < 8; ++j) {
            int c = nb + j * 8 + 2 * tg;
            atomicAdd(p0 + c, acc[i][j][0] + sB2[c]);
            atomicAdd(p0 + c + 1, acc[i][j][1] + sB2[c + 1]);
            atomicAdd(p1 + c, acc[i][j][2] + sB2[c]);
            atomicAdd(p1 + c + 1, acc[i][j][3] + sB2[c + 1]);
        }
    }
}

// ---------------------------------------------------------------------------
// Kernel 3: out = relu([nf|agg] @ U1 + ub1) @ U2 + ub2   (128 rows/block)
// ---------------------------------------------------------------------------
__global__ __launch_bounds__(256, 1) void k_update(const float* __restrict__ nf,
                                                   const float* __restrict__ b1,
                                                   const float* __restrict__ b2,
                                                   float* __restrict__ out) {
    float* fsm = reinterpret_cast<float*>(dyn_smem);
    float* sH = fsm;                       // nf
    float* sE = fsm + 128 * LDA;           // agg
    float* sB = fsm + 2 * 128 * LDA;
    float* sB1 = fsm + 3 * 128 * LDA;
    float* sB2 = sB1 + 128;
    const uint32_t sb0 = smem_u32(dyn_smem);

    const int tid = threadIdx.x, lane = tid & 31, w = tid >> 5;
    const int base = blockIdx.x * 128;

    if (tid < 128) {
        sB1[tid] = b1[tid];
        sB2[tid] = b2[tid];
    }
    for (int i = tid; i < 128 * 32; i += 256) {
        int r = i >> 5, c = (i & 31) * 4;
        int gr = base + r;
        uint4 u0 = make_uint4(0, 0, 0, 0), u1 = u0;
        if (gr < NN) {
            float4 v0 = *reinterpret_cast<const float4*>(nf + (size_t)gr * HID + c);
            float4 v1 = *reinterpret_cast<const float4*>(g_agg + (size_t)gr * HID + c);
            u0 = make_uint4(f2tf(v0.x), f2tf(v0.y), f2tf(v0.z), f2tf(v0.w));
            u1 = make_uint4(f2tf(v1.x), f2tf(v1.y), f2tf(v1.z), f2tf(v1.w));
        }
        *reinterpret_cast<uint4*>(sH + r * LDA + c) = u0;
        *reinterpret_cast<uint4*>(sE + r * LDA + c) = u1;
    }
    for (int i = tid; i < 128 * 32; i += 256) {
        int r = i >> 5, c = (i & 31) * 4;
        *reinterpret_cast<float4*>(sB + r * LDA + c) =
            *reinterpret_cast<const float4*>(g_U1t + (size_t)r * 256 + c);
    }
    __syncthreads();

    const int mb = (w & 3) * 32, nb = (w >> 2) * 64;
    uint32_t aH0 = sb0 + (uint32_t)mb * (LDA * 4) + a_lane_off(lane);
    uint32_t aH1 = aH0 + 16 * LDA * 4;
    uint32_t aE0 = aH0 + 128 * LDA * 4;
    uint32_t aE1 = aE0 + 16 * LDA * 4;
    uint32_t bA[4];
#pragma unroll
    for (int jj = 0; jj < 4; ++jj)
        bA[jj] = sb0 + 2 * 128 * LDA * 4 + (uint32_t)(nb + jj * 16) * (LDA * 4) + b_lane_off(lane);

    const int g = lane >> 2, tg = lane & 3;
    float acc[2][8][4];

    zacc(acc);
    wgemm<16>(aH0, aH1, bA, acc);  // chunk0: A = nf
    __syncthreads();
    for (int i = tid; i < 128 * 32; i += 256) {
        int r = i >> 5, c = (i & 31) * 4;
        *reinterpret_cast<float4*>(sB + r * LDA + c) =
            *reinterpret_cast<const float4*>(g_U1t + (size_t)r * 256 + 128 + c);
    }
    __syncthreads();
    wgemm<16>(aE0, aE1, bA, acc);  // chunk1: A = agg
    __syncthreads();
    for (int i = tid; i < 128 * 32; i += 256) {
        int r = i >> 5, c = (i & 31) * 4;
        *reinterpret_cast<float4*>(sB + r * LDA + c) =
            *reinterpret_cast<const float4*>(g_U2t + (size_t)r * 128 + c);
    }
#pragma unroll
    for (int i = 0; i < 2; ++i) {
        int r0 = mb + i * 16 + g;
#pragma unroll
        for (int j = 0; j < 8; ++j) {
            int c = nb + j * 8 + 2 * tg;
            float2 lo = make_float2(
                __uint_as_float(f2tf(fmaxf(acc[i][j][0] + sB1[c], 0.f))),
                __uint_as_float(f2tf(fmaxf(acc[i][j][1] + sB1[c + 1], 0.f))));
            float2 hi = make_float2(
                __uint_as_float(f2tf(fmaxf(acc[i][j][2] + sB1[c], 0.f))),
                __uint_as_float(f2tf(fmaxf(acc[i][j][3] + sB1[c + 1], 0.f))));
            *reinterpret_cast<float2*>(sH + r0 * LDA + c) = lo;
            *reinterpret_cast<float2*>(sH + (r0 + 8) * LDA + c) = hi;
        }
    }
    __syncthreads();

    zacc(acc);
    wgemm<16>(aH0, aH1, bA, acc);  // final GEMM: A = t
#pragma unroll
    for (int i = 0; i < 2; ++i) {
        int r0 = base + mb + i * 16 + g;
#pragma unroll
        for (int j = 0; j < 8; ++j) {
            int c = nb + j * 8 + 2 * tg;
            if (r0 < NN) {
                *reinterpret_cast<float2*>(out + (size_t)r0 * HID + c) =
                    make_float2(acc[i][j][0] + sB2[c], acc[i][j][1] + sB2[c + 1]);
            }
            if (r0 + 8 < NN) {
                *reinterpret_cast<float2*>(out + (size_t)(r0 + 8) * HID + c) =
                    make_float2(acc[i][j][2] + sB2[c], acc[i][j][3] + sB2[c + 1]);
            }
        }
    }
}

// ---------------------------------------------------------------------------
extern "C" void kernel_launch(void* const* d_in, const int* in_sizes, int n_in,
                              void* d_out, int out_size) {
    const float* node_feats = (const float*)d_in[0];
    const int*   edge_idx   = (const int*)d_in[1];
    const float* edge_feats = (const float*)d_in[2];
    const float* node_W     = (const float*)d_in[3];
    const float* node_b     = (const float*)d_in[4];
    const float* edge_W     = (const float*)d_in[5];
    const float* edge_b     = (const float*)d_in[6];
    const float* msg_W1     = (const float*)d_in[7];
    const float* msg_b1     = (const float*)d_in[8];
    const float* msg_W2     = (const float*)d_in[9];
    const float* msg_b2     = (const float*)d_in[10];
    const float* upd_W1     = (const float*)d_in[11];
    const float* upd_b1     = (const float*)d_in[12];
    const float* upd_W2     = (const float*)d_in[13];
    const float* upd_b2     = (const float*)d_in[14];
    float* out = (float*)d_out;

    const int SMEM_NODE = (2 * 128 * LDA + 128) * 4;
    const int SMEM_UPD  = (3 * 128 * LDA + 2 * 128) * 4;

    cudaFuncSetAttribute(k_node,   cudaFuncAttributeMaxDynamicSharedMemorySize, SMEM_NODE);
    cudaFuncSetAttribute(k_edge,   cudaFuncAttributeMaxDynamicSharedMemorySize, EDGE_SMEM);
    cudaFuncSetAttribute(k_update, cudaFuncAttributeMaxDynamicSharedMemorySize, SMEM_UPD);

    const int NB_NODE = (NN + 127) / 128;  // 391
    const int NB_EDGE = NE / 128;          // 6250

    k_tW<<<128, 256>>>(node_W, edge_W, msg_W1, msg_W2, upd_W1, upd_W2);
    k_zero_agg<<<NN * HID / 4 / 256, 256>>>();
    k_node<<<NB_NODE, 256, SMEM_NODE>>>(node_feats, node_b);
    k_edge<<<NB_EDGE, 256, EDGE_SMEM>>>(edge_idx, edge_feats, edge_b, msg_b1, msg_b2);
    k_update<<<NB_NODE, 256, SMEM_UPD>>>(node_feats, upd_b1, upd_b2, out);
}

// round 5
// speedup vs baseline: 3.7566x; 1.3521x over previous
#include <cuda_runtime.h>
#include <cstdint>

#define HID 128
#define NN 50000
#define NE 800000
#define LDA 132   // floats per smem row (528B: bank-rotating, ldmatrix conflict-free)

extern __shared__ char dyn_smem[];

// ---------------- device scratch (allocation-free rule) ----------------
__device__ float g_h[(size_t)NN * HID];    // node embeddings (tf32-truncated)
__device__ float g_agg[(size_t)NN * HID];  // segment-sum accumulator (fp32)
__device__ float g_nWt[128 * 128];         // node_W^T  [N][K] tf32
__device__ float g_eWt[128 * 64];          // edge_W^T  tf32
__device__ float g_W1t[128 * 256];         // msg_W1^T  tf32
__device__ float g_W2t[128 * 128];         // msg_W2^T  tf32
__device__ float g_U1t[128 * 256];         // upd_W1^T  tf32
__device__ float g_U2t[128 * 128];         // upd_W2^T  tf32

// ======================= warp-MMA helpers (generic PTX) =================
__device__ __forceinline__ uint32_t smem_u32(const void* p) {
    uint32_t a;
    asm("{ .reg .u64 t; cvta.to.shared.u64 t, %1; cvt.u32.u64 %0, t; }"
        : "=r"(a) : "l"(p));
    return a;
}
__device__ __forceinline__ uint32_t f2tf(float f) {
    uint32_t u;
    asm("cvt.rna.tf32.f32 %0, %1;" : "=r"(u) : "f"(f));
    return u;
}
__device__ __forceinline__ void ldsm4(uint32_t r[4], uint32_t addr) {
    asm volatile("ldmatrix.sync.aligned.m8n8.x4.shared.b16 {%0,%1,%2,%3}, [%4];"
                 : "=r"(r[0]), "=r"(r[1]), "=r"(r[2]), "=r"(r[3]) : "r"(addr));
}
__device__ __forceinline__ void mma8(float c[4], const uint32_t a[4],
                                     uint32_t b0, uint32_t b1) {
    asm volatile("mma.sync.aligned.m16n8k8.row.col.f32.tf32.tf32.f32 "
                 "{%0,%1,%2,%3}, {%4,%5,%6,%7}, {%8,%9}, {%0,%1,%2,%3};"
                 : "+f"(c[0]), "+f"(c[1]), "+f"(c[2]), "+f"(c[3])
                 : "r"(a[0]), "r"(a[1]), "r"(a[2]), "r"(a[3]), "r"(b0), "r"(b1));
}
__device__ __forceinline__ void zacc(float acc[2][4][4]) {
#pragma unroll
    for (int i = 0; i < 2; ++i)
#pragma unroll
        for (int j = 0; j < 4; ++j)
#pragma unroll
            for (int k = 0; k < 4; ++k) acc[i][j][k] = 0.f;
}

// Warp GEMM: 32x32 output tile, KSTEPS k-steps of 8.
template <int KSTEPS>
__device__ __forceinline__ void wgemm(uint32_t aA0, uint32_t aA1,
                                      const uint32_t bA[2], float acc[2][4][4]) {
#pragma unroll
    for (int ks = 0; ks < KSTEPS; ++ks) {
        uint32_t a0[4], a1[4];
        ldsm4(a0, aA0 + ks * 32);
        ldsm4(a1, aA1 + ks * 32);
#pragma unroll
        for (int jj = 0; jj < 2; ++jj) {
            uint32_t b[4];
            ldsm4(b, bA[jj] + ks * 32);
            mma8(acc[0][2 * jj],     a0, b[0], b[1]);
            mma8(acc[0][2 * jj + 1], a0, b[2], b[3]);
            mma8(acc[1][2 * jj],     a1, b[0], b[1]);
            mma8(acc[1][2 * jj + 1], a1, b[2], b[3]);
        }
    }
}

// Per-lane ldmatrix address offsets (bytes) within a [128][LDA] smem tile.
__device__ __forceinline__ uint32_t a_lane_off(int lane) {
    int row = (lane & 7) + ((lane & 8) ? 8 : 0);
    return (uint32_t)row * (LDA * 4) + ((lane & 16) ? 16 : 0);
}
__device__ __forceinline__ uint32_t b_lane_off(int lane) {
    int row = (lane & 7) + ((lane & 16) ? 8 : 0);
    return (uint32_t)row * (LDA * 4) + ((lane & 8) ? 16 : 0);
}

// ---------------------------------------------------------------------------
// Prep: transpose + tf32-truncate all weight matrices
// ---------------------------------------------------------------------------
__global__ void k_tW(const float* __restrict__ nW, const float* __restrict__ eW,
                     const float* __restrict__ W1, const float* __restrict__ W2,
                     const float* __restrict__ U1, const float* __restrict__ U2) {
    int t = blockIdx.x * blockDim.x + threadIdx.x;
    int tot = gridDim.x * blockDim.x;
    for (int i = t; i < 128 * 128; i += tot) {
        int n = i >> 7, k = i & 127;
        g_nWt[i] = __uint_as_float(f2tf(nW[k * 128 + n]));
        g_W2t[i] = __uint_as_float(f2tf(W2[k * 128 + n]));
        g_U2t[i] = __uint_as_float(f2tf(U2[k * 128 + n]));
    }
    for (int i = t; i < 128 * 64; i += tot) {
        int n = i >> 6, k = i & 63;
        g_eWt[i] = __uint_as_float(f2tf(eW[k * 128 + n]));
    }
    for (int i = t; i < 128 * 256; i += tot) {
        int n = i >> 8, k = i & 255;
        g_W1t[i] = __uint_as_float(f2tf(W1[k * 128 + n]));
        g_U1t[i] = __uint_as_float(f2tf(U1[k * 128 + n]));
    }
}

__global__ __launch_bounds__(256) void k_zero_agg() {
    size_t i = (size_t)blockIdx.x * 256 + threadIdx.x;
    reinterpret_cast<float4*>(g_agg)[i] = make_float4(0.f, 0.f, 0.f, 0.f);
}

// ---------------------------------------------------------------------------
// Kernel 1: h = tf32(node_feats @ node_W + node_b) -> g_h   (128 rows/block)
// 512 threads, 16 warps: warp tile 32x32  (mw = w&3, nw = w>>2)
// ---------------------------------------------------------------------------
__global__ __launch_bounds__(512, 1) void k_node(const float* __restrict__ nf,
                                                 const float* __restrict__ b) {
    float* fsm = reinterpret_cast<float*>(dyn_smem);
    float* sA = fsm;
    float* sB = fsm + 128 * LDA;
    float* sBias = fsm + 2 * 128 * LDA;
    const uint32_t sb0 = smem_u32(dyn_smem);
    const int tid = threadIdx.x, lane = tid & 31, w = tid >> 5;
    const int base = blockIdx.x * 128;

    if (tid < 128) sBias[tid] = b[tid];
    for (int i = tid; i < 128 * 32; i += 512) {
        int r = i >> 5, c = (i & 31) * 4;
        int gr = base + r;
        uint4 u = make_uint4(0, 0, 0, 0);
        if (gr < NN) {
            float4 v = *reinterpret_cast<const float4*>(nf + (size_t)gr * HID + c);
            u = make_uint4(f2tf(v.x), f2tf(v.y), f2tf(v.z), f2tf(v.w));
        }
        *reinterpret_cast<uint4*>(sA + r * LDA + c) = u;
    }
    for (int i = tid; i < 128 * 32; i += 512) {
        int r = i >> 5, c = (i & 31) * 4;
        *reinterpret_cast<float4*>(sB + r * LDA + c) =
            *reinterpret_cast<const float4*>(g_nWt + (size_t)r * 128 + c);
    }
    __syncthreads();

    const int mb = (w & 3) * 32, nb = (w >> 2) * 32;
    uint32_t aA0 = sb0 + (uint32_t)mb * (LDA * 4) + a_lane_off(lane);
    uint32_t aA1 = aA0 + 16 * LDA * 4;
    uint32_t bA[2];
#pragma unroll
    for (int jj = 0; jj < 2; ++jj)
        bA[jj] = sb0 + 128 * LDA * 4 + (uint32_t)(nb + jj * 16) * (LDA * 4) + b_lane_off(lane);

    float acc[2][4][4];
    zacc(acc);
    wgemm<16>(aA0, aA1, bA, acc);

    const int g = lane >> 2, tg = lane & 3;
#pragma unroll
    for (int i = 0; i < 2; ++i) {
        int r0 = base + mb + i * 16 + g;
#pragma unroll
        for (int j = 0; j < 4; ++j) {
            int c = nb + j * 8 + 2 * tg;
            if (r0 < NN) {
                g_h[(size_t)r0 * HID + c] = __uint_as_float(f2tf(acc[i][j][0] + sBias[c]));
                g_h[(size_t)r0 * HID + c + 1] = __uint_as_float(f2tf(acc[i][j][1] + sBias[c + 1]));
            }
            if (r0 + 8 < NN) {
                g_h[(size_t)(r0 + 8) * HID + c] = __uint_as_float(f2tf(acc[i][j][2] + sBias[c]));
                g_h[(size_t)(r0 + 8) * HID + c + 1] = __uint_as_float(f2tf(acc[i][j][3] + sBias[c + 1]));
            }
        }
    }
}

// ---------------------------------------------------------------------------
// Kernel 2: fused edge pipeline (128 edges/block), 512 threads / 16 warps
// ---------------------------------------------------------------------------
static constexpr int EDGE_SMEM =
    (3 * 128 * LDA + 3 * 128) * 4 + 2 * 128 * 4;

__global__ __launch_bounds__(512, 1) void k_edge(const int* __restrict__ eidx,
                                                 const float* __restrict__ ef,
                                                 const float* __restrict__ eb,
                                                 const float* __restrict__ b1,
                                                 const float* __restrict__ b2) {
    float* fsm = reinterpret_cast<float*>(dyn_smem);
    float* sH = fsm;
    float* sE = fsm + 128 * LDA;
    float* sB = fsm + 2 * 128 * LDA;
    float* sEB = fsm + 3 * 128 * LDA;
    float* sB1 = sEB + 128;
    float* sB2 = sB1 + 128;
    int* sSrc = reinterpret_cast<int*>(sB2 + 128);
    int* sDst = sSrc + 128;
    const uint32_t sb0 = smem_u32(dyn_smem);

    const int tid = threadIdx.x, lane = tid & 31, w = tid >> 5;
    const int e0 = blockIdx.x * 128;

    if (tid < 128) {
        sSrc[tid] = eidx[e0 + tid];
        sDst[tid] = eidx[NE + e0 + tid];
        sEB[tid] = eb[tid];
    } else if (tid < 256) {
        sB1[tid - 128] = b1[tid - 128];
        sB2[tid - 128] = b2[tid - 128];
    }
    // ef [128x64] cvt -> sE cols 0..63
    for (int i = tid; i < 128 * 16; i += 512) {
        int r = i >> 4, c = (i & 15) * 4;
        float4 v = *reinterpret_cast<const float4*>(ef + (size_t)(e0 + r) * 64 + c);
        *reinterpret_cast<uint4*>(sE + r * LDA + c) =
            make_uint4(f2tf(v.x), f2tf(v.y), f2tf(v.z), f2tf(v.w));
    }
    // eWt [128x64] copy -> sB
    for (int i = tid; i < 128 * 16; i += 512) {
        int r = i >> 4, c = (i & 15) * 4;
        *reinterpret_cast<float4*>(sB + r * LDA + c) =
            *reinterpret_cast<const float4*>(g_eWt + (size_t)r * 64 + c);
    }
    __syncthreads();  // sSrc visible
    // gather h[src] (already tf32) -> sH
    for (int i = tid; i < 128 * 32; i += 512) {
        int r = i >> 5, c = (i & 31) * 4;
        *reinterpret_cast<float4*>(sH + r * LDA + c) =
            *reinterpret_cast<const float4*>(g_h + (size_t)sSrc[r] * HID + c);
    }
    __syncthreads();

    const int mb = (w & 3) * 32, nb = (w >> 2) * 32;
    uint32_t aH0 = sb0 + (uint32_t)mb * (LDA * 4) + a_lane_off(lane);
    uint32_t aH1 = aH0 + 16 * LDA * 4;
    uint32_t aE0 = aH0 + 128 * LDA * 4;
    uint32_t aE1 = aE0 + 16 * LDA * 4;
    uint32_t bA[2];
#pragma unroll
    for (int jj = 0; jj < 2; ++jj)
        bA[jj] = sb0 + 2 * 128 * LDA * 4 + (uint32_t)(nb + jj * 16) * (LDA * 4) + b_lane_off(lane);

    const int g = lane >> 2, tg = lane & 3;
    float acc[2][4][4];

    // ---- GEMM0: e = ef @ eWt^T  (K=64) ----
    zacc(acc);
    wgemm<8>(aE0, aE1, bA, acc);
    __syncthreads();
    // stage W1 ch0 -> sB ; epilogue e -> sE
    for (int i = tid; i < 128 * 32; i += 512) {
        int r = i >> 5, c = (i & 31) * 4;
        *reinterpret_cast<float4*>(sB + r * LDA + c) =
            *reinterpret_cast<const float4*>(g_W1t + (size_t)r * 256 + c);
    }
#pragma unroll
    for (int i = 0; i < 2; ++i) {
        int r0 = mb + i * 16 + g;
#pragma unroll
        for (int j = 0; j < 4; ++j) {
            int c = nb + j * 8 + 2 * tg;
            float2 lo = make_float2(__uint_as_float(f2tf(acc[i][j][0] + sEB[c])),
                                    __uint_as_float(f2tf(acc[i][j][1] + sEB[c + 1])));
            float2 hi = make_float2(__uint_as_float(f2tf(acc[i][j][2] + sEB[c])),
                                    __uint_as_float(f2tf(acc[i][j][3] + sEB[c + 1])));
            *reinterpret_cast<float2*>(sE + r0 * LDA + c) = lo;
            *reinterpret_cast<float2*>(sE + (r0 + 8) * LDA + c) = hi;
        }
    }
    __syncthreads();

    // ---- GEMM1: t = relu([h|e] @ W1t^T + b1)  (K=256 in 2 chunks) ----
    zacc(acc);
    wgemm<16>(aH0, aH1, bA, acc);  // chunk0: A = h
    __syncthreads();
    for (int i = tid; i < 128 * 32; i += 512) {
        int r = i >> 5, c = (i & 31) * 4;
        *reinterpret_cast<float4*>(sB + r * LDA + c) =
            *reinterpret_cast<const float4*>(g_W1t + (size_t)r * 256 + 128 + c);
    }
    __syncthreads();
    wgemm<16>(aE0, aE1, bA, acc);  // chunk1: A = e
    __syncthreads();
    // stage W2 -> sB ; epilogue t = relu(acc+b1) -> sH
    for (int i = tid; i < 128 * 32; i += 512) {
        int r = i >> 5, c = (i & 31) * 4;
        *reinterpret_cast<float4*>(sB + r * LDA + c) =
            *reinterpret_cast<const float4*>(g_W2t + (size_t)r * 128 + c);
    }
#pragma unroll
    for (int i = 0; i < 2; ++i) {
        int r0 = mb + i * 16 + g;
#pragma unroll
        for (int j = 0; j < 4; ++j) {
            int c = nb + j * 8 + 2 * tg;
            float2 lo = make_float2(
                __uint_as_float(f2tf(fmaxf(acc[i][j][0] + sB1[c], 0.f))),
                __uint_as_float(f2tf(fmaxf(acc[i][j][1] + sB1[c + 1], 0.f))));
            float2 hi = make_float2(
                __uint_as_float(f2tf(fmaxf(acc[i][j][2] + sB1[c], 0.f))),
                __uint_as_float(f2tf(fmaxf(acc[i][j][3] + sB1[c + 1], 0.f))));
            *reinterpret_cast<float2*>(sH + r0 * LDA + c) = lo;
            *reinterpret_cast<float2*>(sH + (r0 + 8) * LDA + c) = hi;
        }
    }
    __syncthreads();

    // ---- GEMM2: m = t @ W2t^T + b2  (K=128) -> scatter-add ----
    zacc(acc);
    wgemm<16>(aH0, aH1, bA, acc);
#pragma unroll
    for (int i = 0; i < 2; ++i) {
        int r0 = mb + i * 16 + g;
        float* p0 = g_agg + (size_t)sDst[r0] * HID;
        float* p1 = g_agg + (size_t)sDst[r0 + 8] * HID;
#pragma unroll
        for (int j = 0; j < 4; ++j) {
            int c = nb + j * 8 + 2 * tg;
            atomicAdd(p0 + c, acc[i][j][0] + sB2[c]);
            atomicAdd(p0 + c + 1, acc[i][j][1] + sB2[c + 1]);
            atomicAdd(p1 + c, acc[i][j][2] + sB2[c]);
            atomicAdd(p1 + c + 1, acc[i][j][3] + sB2[c + 1]);
        }
    }
}

// ---------------------------------------------------------------------------
// Kernel 3: out = relu([nf|agg] @ U1 + ub1) @ U2 + ub2   (512 threads)
// ---------------------------------------------------------------------------
__global__ __launch_bounds__(512, 1) void k_update(const float* __restrict__ nf,
                                                   const float* __restrict__ b1,
                                                   const float* __restrict__ b2,
                                                   float* __restrict__ out) {
    float* fsm = reinterpret_cast<float*>(dyn_smem);
    float* sH = fsm;                       // nf
    float* sE = fsm + 128 * LDA;           // agg
    float* sB = fsm + 2 * 128 * LDA;
    float* sB1 = fsm + 3 * 128 * LDA;
    float* sB2 = sB1 + 128;
    const uint32_t sb0 = smem_u32(dyn_smem);

    const int tid = threadIdx.x, lane = tid & 31, w = tid >> 5;
    const int base = blockIdx.x * 128;

    if (tid < 128) {
        sB1[tid] = b1[tid];
        sB2[tid] = b2[tid];
    }
    for (int i = tid; i < 128 * 32; i += 512) {
        int r = i >> 5, c = (i & 31) * 4;
        int gr = base + r;
        uint4 u0 = make_uint4(0, 0, 0, 0), u1 = u0;
        if (gr < NN) {
            float4 v0 = *reinterpret_cast<const float4*>(nf + (size_t)gr * HID + c);
            float4 v1 = *reinterpret_cast<const float4*>(g_agg + (size_t)gr * HID + c);
            u0 = make_uint4(f2tf(v0.x), f2tf(v0.y), f2tf(v0.z), f2tf(v0.w));
            u1 = make_uint4(f2tf(v1.x), f2tf(v1.y), f2tf(v1.z), f2tf(v1.w));
        }
        *reinterpret_cast<uint4*>(sH + r * LDA + c) = u0;
        *reinterpret_cast<uint4*>(sE + r * LDA + c) = u1;
    }
    for (int i = tid; i < 128 * 32; i += 512) {
        int r = i >> 5, c = (i & 31) * 4;
        *reinterpret_cast<float4*>(sB + r * LDA + c) =
            *reinterpret_cast<const float4*>(g_U1t + (size_t)r * 256 + c);
    }
    __syncthreads();

    const int mb = (w & 3) * 32, nb = (w >> 2) * 32;
    uint32_t aH0 = sb0 + (uint32_t)mb * (LDA * 4) + a_lane_off(lane);
    uint32_t aH1 = aH0 + 16 * LDA * 4;
    uint32_t aE0 = aH0 + 128 * LDA * 4;
    uint32_t aE1 = aE0 + 16 * LDA * 4;
    uint32_t bA[2];
#pragma unroll
    for (int jj = 0; jj < 2; ++jj)
        bA[jj] = sb0 + 2 * 128 * LDA * 4 + (uint32_t)(nb + jj * 16) * (LDA * 4) + b_lane_off(lane);

    const int g = lane >> 2, tg = lane & 3;
    float acc[2][4][4];

    zacc(acc);
    wgemm<16>(aH0, aH1, bA, acc);  // chunk0: A = nf
    __syncthreads();
    for (int i = tid; i < 128 * 32; i += 512) {
        int r = i >> 5, c = (i & 31) * 4;
        *reinterpret_cast<float4*>(sB + r * LDA + c) =
            *reinterpret_cast<const float4*>(g_U1t + (size_t)r * 256 + 128 + c);
    }
    __syncthreads();
    wgemm<16>(aE0, aE1, bA, acc);  // chunk1: A = agg
    __syncthreads();
    for (int i = tid; i < 128 * 32; i += 512) {
        int r = i >> 5, c = (i & 31) * 4;
        *reinterpret_cast<float4*>(sB + r * LDA + c) =
            *reinterpret_cast<const float4*>(g_U2t + (size_t)r * 128 + c);
    }
#pragma unroll
    for (int i = 0; i < 2; ++i) {
        int r0 = mb + i * 16 + g;
#pragma unroll
        for (int j = 0; j < 4; ++j) {
            int c = nb + j * 8 + 2 * tg;
            float2 lo = make_float2(
                __uint_as_float(f2tf(fmaxf(acc[i][j][0] + sB1[c], 0.f))),
                __uint_as_float(f2tf(fmaxf(acc[i][j][1] + sB1[c + 1], 0.f))));
            float2 hi = make_float2(
                __uint_as_float(f2tf(fmaxf(acc[i][j][2] + sB1[c], 0.f))),
                __uint_as_float(f2tf(fmaxf(acc[i][j][3] + sB1[c + 1], 0.f))));
            *reinterpret_cast<float2*>(sH + r0 * LDA + c) = lo;
            *reinterpret_cast<float2*>(sH + (r0 + 8) * LDA + c) = hi;
        }
    }
    __syncthreads();

    zacc(acc);
    wgemm<16>(aH0, aH1, bA, acc);  // final GEMM: A = t
#pragma unroll
    for (int i = 0; i < 2; ++i) {
        int r0 = base + mb + i * 16 + g;
#pragma unroll
        for (int j = 0; j < 4; ++j) {
            int c = nb + j * 8 + 2 * tg;
            if (r0 < NN) {
                *reinterpret_cast<float2*>(out + (size_t)r0 * HID + c) =
                    make_float2(acc[i][j][0] + sB2[c], acc[i][j][1] + sB2[c + 1]);
            }
            if (r0 + 8 < NN) {
                *reinterpret_cast<float2*>(out + (size_t)(r0 + 8) * HID + c) =
                    make_float2(acc[i][j][2] + sB2[c], acc[i][j][3] + sB2[c + 1]);
            }
        }
    }
}

// ---------------------------------------------------------------------------
extern "C" void kernel_launch(void* const* d_in, const int* in_sizes, int n_in,
                              void* d_out, int out_size) {
    const float* node_feats = (const float*)d_in[0];
    const int*   edge_idx   = (const int*)d_in[1];
    const float* edge_feats = (const float*)d_in[2];
    const float* node_W     = (const float*)d_in[3];
    const float* node_b     = (const float*)d_in[4];
    const float* edge_W     = (const float*)d_in[5];
    const float* edge_b     = (const float*)d_in[6];
    const float* msg_W1     = (const float*)d_in[7];
    const float* msg_b1     = (const float*)d_in[8];
    const float* msg_W2     = (const float*)d_in[9];
    const float* msg_b2     = (const float*)d_in[10];
    const float* upd_W1     = (const float*)d_in[11];
    const float* upd_b1     = (const float*)d_in[12];
    const float* upd_W2     = (const float*)d_in[13];
    const float* upd_b2     = (const float*)d_in[14];
    float* out = (float*)d_out;

    const int SMEM_NODE = (2 * 128 * LDA + 128) * 4;
    const int SMEM_UPD  = (3 * 128 * LDA + 2 * 128) * 4;

    cudaFuncSetAttribute(k_node,   cudaFuncAttributeMaxDynamicSharedMemorySize, SMEM_NODE);
    cudaFuncSetAttribute(k_edge,   cudaFuncAttributeMaxDynamicSharedMemorySize, EDGE_SMEM);
    cudaFuncSetAttribute(k_update, cudaFuncAttributeMaxDynamicSharedMemorySize, SMEM_UPD);

    const int NB_NODE = (NN + 127) / 128;  // 391
    const int NB_EDGE = NE / 128;          // 6250

    k_tW<<<128, 256>>>(node_W, edge_W, msg_W1, msg_W2, upd_W1, upd_W2);
    k_zero_agg<<<NN * HID / 4 / 256, 256>>>();
    k_node<<<NB_NODE, 512, SMEM_NODE>>>(node_feats, node_b);
    k_edge<<<NB_EDGE, 512, EDGE_SMEM>>>(edge_idx, edge_feats, edge_b, msg_b1, msg_b2);
    k_update<<<NB_NODE, 512, SMEM_UPD>>>(node_feats, upd_b1, upd_b2, out);
}

// round 8
// speedup vs baseline: 5.2195x; 1.3894x over previous
#include <cuda_runtime.h>
#include <cstdint>

#define HID 128
#define NN 50000
#define NE 800000
#define LDA 132   // floats per smem A row (528B, bank-rotating, ldmatrix conflict-free)
#define LDB 68    // floats per smem B row in K=64 chunk buffers (272B)

extern __shared__ char dyn_smem[];

// ---------------- device scratch (allocation-free rule) ----------------
__device__ float g_h[(size_t)NN * HID];    // node embeddings (tf32-truncated)
__device__ float g_agg[(size_t)NN * HID];  // segment-sum accumulator (fp32)
__device__ float g_nWt[128 * 128];         // node_W^T  [N][K] tf32
__device__ float g_eWt[128 * 64];          // edge_W^T  tf32
__device__ float g_W1t[128 * 256];         // msg_W1^T  tf32
__device__ float g_W2t[128 * 128];         // msg_W2^T  tf32
__device__ float g_U1t[128 * 256];         // upd_W1^T  tf32
__device__ float g_U2t[128 * 128];         // upd_W2^T  tf32

// ======================= helpers (generic PTX) =========================
__device__ __forceinline__ uint32_t smem_u32(const void* p) {
    uint32_t a;
    asm("{ .reg .u64 t; cvta.to.shared.u64 t, %1; cvt.u32.u64 %0, t; }"
        : "=r"(a) : "l"(p));
    return a;
}
__device__ __forceinline__ uint32_t f2tf(float f) {
    uint32_t u;
    asm("cvt.rna.tf32.f32 %0, %1;" : "=r"(u) : "f"(f));
    return u;
}
__device__ __forceinline__ void ldsm4(uint32_t r[4], uint32_t addr) {
    asm volatile("ldmatrix.sync.aligned.m8n8.x4.shared.b16 {%0,%1,%2,%3}, [%4];"
                 : "=r"(r[0]), "=r"(r[1]), "=r"(r[2]), "=r"(r[3]) : "r"(addr));
}
__device__ __forceinline__ void mma8(float c[4], const uint32_t a[4],
                                     uint32_t b0, uint32_t b1) {
    asm volatile("mma.sync.aligned.m16n8k8.row.col.f32.tf32.tf32.f32 "
                 "{%0,%1,%2,%3}, {%4,%5,%6,%7}, {%8,%9}, {%0,%1,%2,%3};"
                 : "+f"(c[0]), "+f"(c[1]), "+f"(c[2]), "+f"(c[3])
                 : "r"(a[0]), "r"(a[1]), "r"(a[2]), "r"(a[3]), "r"(b0), "r"(b1));
}
#define CP16(dst, src) \
    asm volatile("cp.async.cg.shared.global [%0], [%1], 16;" :: "r"(dst), "l"(src))
#define CP_COMMIT() asm volatile("cp.async.commit_group;" ::: "memory")
#define CP_WAIT(n)  asm volatile("cp.async.wait_group %0;" :: "n"(n) : "memory")

__device__ __forceinline__ void zacc(float acc[2][4][4]) {
#pragma unroll
    for (int i = 0; i < 2; ++i)
#pragma unroll
        for (int j = 0; j < 4; ++j)
#pragma unroll
            for (int k = 0; k < 4; ++k) acc[i][j][k] = 0.f;
}

// Warp GEMM: 32x32 output tile, KSTEPS k-steps of 8.
template <int KSTEPS>
__device__ __forceinline__ void wgemm(uint32_t aA0, uint32_t aA1,
                                      const uint32_t bA[2], float acc[2][4][4]) {
#pragma unroll
    for (int ks = 0; ks < KSTEPS; ++ks) {
        uint32_t a0[4], a1[4];
        ldsm4(a0, aA0 + ks * 32);
        ldsm4(a1, aA1 + ks * 32);
#pragma unroll
        for (int jj = 0; jj < 2; ++jj) {
            uint32_t b[4];
            ldsm4(b, bA[jj] + ks * 32);
            mma8(acc[0][2 * jj],     a0, b[0], b[1]);
            mma8(acc[0][2 * jj + 1], a0, b[2], b[3]);
            mma8(acc[1][2 * jj],     a1, b[0], b[1]);
            mma8(acc[1][2 * jj + 1], a1, b[2], b[3]);
        }
    }
}

__device__ __forceinline__ uint32_t a_lane_off(int lane) {
    int row = (lane & 7) + ((lane & 8) ? 8 : 0);
    return (uint32_t)row * (LDA * 4) + ((lane & 16) ? 16 : 0);
}
__device__ __forceinline__ uint32_t b_lane_off_ldb(int lane) {
    int row = (lane & 7) + ((lane & 16) ? 8 : 0);
    return (uint32_t)row * (LDB * 4) + ((lane & 8) ? 16 : 0);
}
__device__ __forceinline__ uint32_t b_lane_off_lda(int lane) {
    int row = (lane & 7) + ((lane & 16) ? 8 : 0);
    return (uint32_t)row * (LDA * 4) + ((lane & 8) ? 16 : 0);
}

// cp.async a [128n x 64k] weight chunk (row stride srcK floats) into B buffer
__device__ __forceinline__ void stage_chunk(uint32_t dstB, const float* srcBase,
                                            int srcK, int tid) {
#pragma unroll
    for (int i = tid; i < 128 * 16; i += 512) {
        int n = i >> 4, k4 = (i & 15) * 4;
        CP16(dstB + (uint32_t)(n * LDB + k4) * 4, srcBase + (size_t)n * srcK + k4);
    }
}

// ---------------------------------------------------------------------------
// Prep: transpose + tf32-truncate all weight matrices
// ---------------------------------------------------------------------------
__global__ void k_tW(const float* __restrict__ nW, const float* __restrict__ eW,
                     const float* __restrict__ W1, const float* __restrict__ W2,
                     const float* __restrict__ U1, const float* __restrict__ U2) {
    int t = blockIdx.x * blockDim.x + threadIdx.x;
    int tot = gridDim.x * blockDim.x;
    for (int i = t; i < 128 * 128; i += tot) {
        int n = i >> 7, k = i & 127;
        g_nWt[i] = __uint_as_float(f2tf(nW[k * 128 + n]));
        g_W2t[i] = __uint_as_float(f2tf(W2[k * 128 + n]));
        g_U2t[i] = __uint_as_float(f2tf(U2[k * 128 + n]));
    }
    for (int i = t; i < 128 * 64; i += tot) {
        int n = i >> 6, k = i & 63;
        g_eWt[i] = __uint_as_float(f2tf(eW[k * 128 + n]));
    }
    for (int i = t; i < 128 * 256; i += tot) {
        int n = i >> 8, k = i & 255;
        g_W1t[i] = __uint_as_float(f2tf(W1[k * 128 + n]));
        g_U1t[i] = __uint_as_float(f2tf(U1[k * 128 + n]));
    }
}

__global__ __launch_bounds__(256) void k_zero_agg() {
    size_t i = (size_t)blockIdx.x * 256 + threadIdx.x;
    reinterpret_cast<float4*>(g_agg)[i] = make_float4(0.f, 0.f, 0.f, 0.f);
}

// ---------------------------------------------------------------------------
// Kernel 1: h = tf32(node_feats @ node_W + node_b) -> g_h
// ---------------------------------------------------------------------------
__global__ __launch_bounds__(512, 1) void k_node(const float* __restrict__ nf,
                                                 const float* __restrict__ b) {
    float* fsm = reinterpret_cast<float*>(dyn_smem);
    float* sA = fsm;
    float* sB = fsm + 128 * LDA;
    float* sBias = fsm + 2 * 128 * LDA;
    const uint32_t sb0 = smem_u32(dyn_smem);
    const int tid = threadIdx.x, lane = tid & 31, w = tid >> 5;
    const int base = blockIdx.x * 128;

    if (tid < 128) sBias[tid] = b[tid];
    for (int i = tid; i < 128 * 32; i += 512) {
        int r = i >> 5, c = (i & 31) * 4;
        int gr = base + r;
        uint4 u = make_uint4(0, 0, 0, 0);
        if (gr < NN) {
            float4 v = *reinterpret_cast<const float4*>(nf + (size_t)gr * HID + c);
            u = make_uint4(f2tf(v.x), f2tf(v.y), f2tf(v.z), f2tf(v.w));
        }
        *reinterpret_cast<uint4*>(sA + r * LDA + c) = u;
    }
    for (int i = tid; i < 128 * 32; i += 512) {
        int r = i >> 5, c = (i & 31) * 4;
        *reinterpret_cast<float4*>(sB + r * LDA + c) =
            *reinterpret_cast<const float4*>(g_nWt + (size_t)r * 128 + c);
    }
    __syncthreads();

    const int mb = (w & 3) * 32, nb = (w >> 2) * 32;
    uint32_t aA0 = sb0 + (uint32_t)mb * (LDA * 4) + a_lane_off(lane);
    uint32_t aA1 = aA0 + 16 * LDA * 4;
    uint32_t bA[2];
#pragma unroll
    for (int jj = 0; jj < 2; ++jj)
        bA[jj] = sb0 + 128 * LDA * 4 + (uint32_t)(nb + jj * 16) * (LDA * 4) + b_lane_off_lda(lane);

    float acc[2][4][4];
    zacc(acc);
    wgemm<16>(aA0, aA1, bA, acc);

    const int g = lane >> 2, tg = lane & 3;
#pragma unroll
    for (int i = 0; i < 2; ++i) {
        int r0 = base + mb + i * 16 + g;
#pragma unroll
        for (int j = 0; j < 4; ++j) {
            int c = nb + j * 8 + 2 * tg;
            if (r0 < NN) {
                g_h[(size_t)r0 * HID + c] = __uint_as_float(f2tf(acc[i][j][0] + sBias[c]));
                g_h[(size_t)r0 * HID + c + 1] = __uint_as_float(f2tf(acc[i][j][1] + sBias[c + 1]));
            }
            if (r0 + 8 < NN) {
                g_h[(size_t)(r0 + 8) * HID + c] = __uint_as_float(f2tf(acc[i][j][2] + sBias[c]));
                g_h[(size_t)(r0 + 8) * HID + c + 1] = __uint_as_float(f2tf(acc[i][j][3] + sBias[c + 1]));
            }
        }
    }
}

// ---------------------------------------------------------------------------
// Kernel 2: fused edge pipeline, cp.async-streamed weights (K=64 chunks).
// Every consume of cp.async data happens after CP_WAIT + __syncthreads().
// ---------------------------------------------------------------------------
static constexpr int SH_B  = 0;
static constexpr int SE_B  = 128 * LDA * 4;            // 67584
static constexpr int B0_B  = SE_B * 2;                 // 135168
static constexpr int B1_B  = B0_B + 128 * LDB * 4;     // +34816
static constexpr int MISC_B = B1_B + 128 * LDB * 4;    // 204800
static constexpr int EDGE_SMEM = MISC_B + 4 * 128 * 4; // 206848

__global__ __launch_bounds__(512, 1) void k_edge(const int* __restrict__ eidx,
                                                 const float* __restrict__ ef,
                                                 const float* __restrict__ eb,
                                                 const float* __restrict__ b1,
                                                 const float* __restrict__ b2) {
    char* smem = dyn_smem;
    float* sH = reinterpret_cast<float*>(smem + SH_B);
    float* sE = reinterpret_cast<float*>(smem + SE_B);
    float* sEB = reinterpret_cast<float*>(smem + MISC_B);
    float* sB1b = sEB + 128;
    float* sB2b = sB1b + 128;
    int* sDst = reinterpret_cast<int*>(sB2b + 128);
    const uint32_t sb0 = smem_u32(smem);

    const int tid = threadIdx.x, lane = tid & 31, w = tid >> 5;
    const int e0 = blockIdx.x * 128;

    // biases + dst indices (published by first __syncthreads)
    if (tid < 128) {
        sDst[tid] = eidx[NE + e0 + tid];
        sEB[tid] = eb[tid];
    } else if (tid < 256) {
        sB1b[tid - 128] = b1[tid - 128];
        sB2b[tid - 128] = b2[tid - 128];
    }

    // group0: c0 = eWt -> B0
    stage_chunk(sb0 + B0_B, g_eWt, 64, tid);
    CP_COMMIT();
    // group1: gather h[src] -> sH  (FIXED: 32 x 16B segments per 128-float row)
#pragma unroll
    for (int i = tid; i < 128 * 32; i += 512) {
        int r = i >> 5, s = i & 31;
        int src = eidx[e0 + r];
        CP16(sb0 + SH_B + (uint32_t)(r * LDA * 4 + s * 16),
             g_h + (size_t)src * HID + s * 4);
    }
    CP_COMMIT();
    // group2: c1 = W1t[:,0:64] -> B1
    stage_chunk(sb0 + B1_B, g_W1t, 256, tid);
    CP_COMMIT();

    // ef [128x64] cvt -> sE cols 0..63 (manual: needs tf32 conversion)
#pragma unroll
    for (int i = tid; i < 128 * 16; i += 512) {
        int r = i >> 4, c = (i & 15) * 4;
        float4 v = *reinterpret_cast<const float4*>(ef + (size_t)(e0 + r) * 64 + c);
        *reinterpret_cast<uint4*>(sE + r * LDA + c) =
            make_uint4(f2tf(v.x), f2tf(v.y), f2tf(v.z), f2tf(v.w));
    }

    const int mb = (w & 3) * 32, nb = (w >> 2) * 32;
    uint32_t aH0 = sb0 + SH_B + (uint32_t)mb * (LDA * 4) + a_lane_off(lane);
    uint32_t aH1 = aH0 + 16 * LDA * 4;
    uint32_t aE0 = sb0 + SE_B + (uint32_t)mb * (LDA * 4) + a_lane_off(lane);
    uint32_t aE1 = aE0 + 16 * LDA * 4;
    uint32_t b0A[2], b1A[2];
#pragma unroll
    for (int jj = 0; jj < 2; ++jj) {
        uint32_t off = (uint32_t)(nb + jj * 16) * (LDB * 4) + b_lane_off_ldb(lane);
        b0A[jj] = sb0 + B0_B + off;
        b1A[jj] = sb0 + B1_B + off;
    }

    const int g = lane >> 2, tg = lane & 3;
    float acc[2][4][4];

    // ---- phase 0: GEMM0 e = ef @ eWt (c0 in B0) ----
    CP_WAIT(2);          // c0 complete (own copies)
    __syncthreads();     // publish c0 + ef + biases
    zacc(acc);
    wgemm<8>(aE0, aE1, b0A, acc);

    CP_WAIT(0);          // gather + c1 complete
    __syncthreads();     // publish sH, c1; certify B0 + sE(ef) free
    stage_chunk(sb0 + B0_B, g_W1t + 64, 256, tid);  // prefetch c2 -> B0
    CP_COMMIT();

    // epilogue0: e = acc + eb -> sE (consumed two phases later)
#pragma unroll
    for (int i = 0; i < 2; ++i) {
        int r0 = mb + i * 16 + g;
#pragma unroll
        for (int j = 0; j < 4; ++j) {
            int c = nb + j * 8 + 2 * tg;
            float2 lo = make_float2(__uint_as_float(f2tf(acc[i][j][0] + sEB[c])),
                                    __uint_as_float(f2tf(acc[i][j][1] + sEB[c + 1])));
            float2 hi = make_float2(__uint_as_float(f2tf(acc[i][j][2] + sEB[c])),
                                    __uint_as_float(f2tf(acc[i][j][3] + sEB[c + 1])));
            *reinterpret_cast<float2*>(sE + r0 * LDA + c) = lo;
            *reinterpret_cast<float2*>(sE + (r0 + 8) * LDA + c) = hi;
        }
    }

    // ---- GEMM1: t = relu([h|e] @ W1t + b1), 4 chunks ----
    zacc(acc);
    wgemm<8>(aH0, aH1, b1A, acc);                 // c1: h k0:64
    CP_WAIT(0);
    __syncthreads();                              // publish c2 + epilogue0(sE); B1 free
    stage_chunk(sb0 + B1_B, g_W1t + 128, 256, tid);  // prefetch c3 -> B1
    CP_COMMIT();
    wgemm<8>(aH0 + 256, aH1 + 256, b0A, acc);     // c2: h k64:128
    CP_WAIT(0);
    __syncthreads();                              // publish c3; B0 free
    stage_chunk(sb0 + B0_B, g_W1t + 192, 256, tid);  // prefetch c4 -> B0
    CP_COMMIT();
    wgemm<8>(aE0, aE1, b1A, acc);                 // c3: e k0:64
    CP_WAIT(0);
    __syncthreads();                              // publish c4; B1 free
    stage_chunk(sb0 + B1_B, g_W2t, 128, tid);     // prefetch c5 -> B1
    CP_COMMIT();
    wgemm<8>(aE0 + 256, aE1 + 256, b0A, acc);     // c4: e k64:128
    CP_WAIT(0);
    __syncthreads();                              // publish c5; B0 free
    stage_chunk(sb0 + B0_B, g_W2t + 64, 128, tid);  // prefetch c6 -> B0
    CP_COMMIT();

    // epilogue1: t = relu(acc + b1) -> sH  (sH reads done: last at c2)
#pragma unroll
    for (int i = 0; i < 2; ++i) {
        int r0 = mb + i * 16 + g;
#pragma unroll
        for (int j = 0; j < 4; ++j) {
            int c = nb + j * 8 + 2 * tg;
            float2 lo = make_float2(
                __uint_as_float(f2tf(fmaxf(acc[i][j][0] + sB1b[c], 0.f))),
                __uint_as_float(f2tf(fmaxf(acc[i][j][1] + sB1b[c + 1], 0.f))));
            float2 hi = make_float2(
                __uint_as_float(f2tf(fmaxf(acc[i][j][2] + sB1b[c], 0.f))),
                __uint_as_float(f2tf(fmaxf(acc[i][j][3] + sB1b[c + 1], 0.f))));
            *reinterpret_cast<float2*>(sH + r0 * LDA + c) = lo;
            *reinterpret_cast<float2*>(sH + (r0 + 8) * LDA + c) = hi;
        }
    }
    __syncthreads();                              // publish t (c5 already published)

    // ---- GEMM2: m = t @ W2t + b2 (K=128) ----
    zacc(acc);
    wgemm<8>(aH0, aH1, b1A, acc);                 // c5: t k0:64
    CP_WAIT(0);
    __syncthreads();                              // publish c6
    wgemm<8>(aH0 + 256, aH1 + 256, b0A, acc);     // c6: t k64:128

    // scatter-add into g_agg[dst]
#pragma unroll
    for (int i = 0; i < 2; ++i) {
        int r0 = mb + i * 16 + g;
        float* p0 = g_agg + (size_t)sDst[r0] * HID;
        float* p1 = g_agg + (size_t)sDst[r0 + 8] * HID;
#pragma unroll
        for (int j = 0; j < 4; ++j) {
            int c = nb + j * 8 + 2 * tg;
            atomicAdd(p0 + c, acc[i][j][0] + sB2b[c]);
            atomicAdd(p0 + c + 1, acc[i][j][1] + sB2b[c + 1]);
            atomicAdd(p1 + c, acc[i][j][2] + sB2b[c]);
            atomicAdd(p1 + c + 1, acc[i][j][3] + sB2b[c + 1]);
        }
    }
}

// ---------------------------------------------------------------------------
// Kernel 3: out = relu([nf|agg] @ U1 + ub1) @ U2 + ub2
// ---------------------------------------------------------------------------
__global__ __launch_bounds__(512, 1) void k_update(const float* __restrict__ nf,
                                                   const float* __restrict__ b1,
                                                   const float* __restrict__ b2,
                                                   float* __restrict__ out) {
    float* fsm = reinterpret_cast<float*>(dyn_smem);
    float* sH = fsm;
    float* sE = fsm + 128 * LDA;
    float* sB = fsm + 2 * 128 * LDA;
    float* sB1 = fsm + 3 * 128 * LDA;
    float* sB2 = sB1 + 128;
    const uint32_t sb0 = smem_u32(dyn_smem);

    const int tid = threadIdx.x, lane = tid & 31, w = tid >> 5;
    const int base = blockIdx.x * 128;

    if (tid < 128) {
        sB1[tid] = b1[tid];
        sB2[tid] = b2[tid];
    }
    for (int i = tid; i < 128 * 32; i += 512) {
        int r = i >> 5, c = (i & 31) * 4;
        int gr = base + r;
        uint4 u0 = make_uint4(0, 0, 0, 0), u1 = u0;
        if (gr < NN) {
            float4 v0 = *reinterpret_cast<const float4*>(nf + (size_t)gr * HID + c);
            float4 v1 = *reinterpret_cast<const float4*>(g_agg + (size_t)gr * HID + c);
            u0 = make_uint4(f2tf(v0.x), f2tf(v0.y), f2tf(v0.z), f2tf(v0.w));
            u1 = make_uint4(f2tf(v1.x), f2tf(v1.y), f2tf(v1.z), f2tf(v1.w));
        }
        *reinterpret_cast<uint4*>(sH + r * LDA + c) = u0;
        *reinterpret_cast<uint4*>(sE + r * LDA + c) = u1;
    }
    for (int i = tid; i < 128 * 32; i += 512) {
        int r = i >> 5, c = (i & 31) * 4;
        *reinterpret_cast<float4*>(sB + r * LDA + c) =
            *reinterpret_cast<const float4*>(g_U1t + (size_t)r * 256 + c);
    }
    __syncthreads();

    const int mb = (w & 3) * 32, nb = (w >> 2) * 32;
    uint32_t aH0 = sb0 + (uint32_t)mb * (LDA * 4) + a_lane_off(lane);
    uint32_t aH1 = aH0 + 16 * LDA * 4;
    uint32_t aE0 = aH0 + 128 * LDA * 4;
    uint32_t aE1 = aE0 + 16 * LDA * 4;
    uint32_t bA[2];
#pragma unroll
    for (int jj = 0; jj < 2; ++jj)
        bA[jj] = sb0 + 2 * 128 * LDA * 4 + (uint32_t)(nb + jj * 16) * (LDA * 4) + b_lane_off_lda(lane);

    const int g = lane >> 2, tg = lane & 3;
    float acc[2][4][4];

    zacc(acc);
    wgemm<16>(aH0, aH1, bA, acc);  // chunk0: A = nf
    __syncthreads();
    for (int i = tid; i < 128 * 32; i += 512) {
        int r = i >> 5, c = (i & 31) * 4;
        *reinterpret_cast<float4*>(sB + r * LDA + c) =
            *reinterpret_cast<const float4*>(g_U1t + (size_t)r * 256 + 128 + c);
    }
    __syncthreads();
    wgemm<16>(aE0, aE1, bA, acc);  // chunk1: A = agg
    __syncthreads();
    for (int i = tid; i < 128 * 32; i += 512) {
        int r = i >> 5, c = (i & 31) * 4;
        *reinterpret_cast<float4*>(sB + r * LDA + c) =
            *reinterpret_cast<const float4*>(g_U2t + (size_t)r * 128 + c);
    }
#pragma unroll
    for (int i = 0; i < 2; ++i) {
        int r0 = mb + i * 16 + g;
#pragma unroll
        for (int j = 0; j < 4; ++j) {
            int c = nb + j * 8 + 2 * tg;
            float2 lo = make_float2(
                __uint_as_float(f2tf(fmaxf(acc[i][j][0] + sB1[c], 0.f))),
                __uint_as_float(f2tf(fmaxf(acc[i][j][1] + sB1[c + 1], 0.f))));
            float2 hi = make_float2(
                __uint_as_float(f2tf(fmaxf(acc[i][j][2] + sB1[c], 0.f))),
                __uint_as_float(f2tf(fmaxf(acc[i][j][3] + sB1[c + 1], 0.f))));
            *reinterpret_cast<float2*>(sH + r0 * LDA + c) = lo;
            *reinterpret_cast<float2*>(sH + (r0 + 8) * LDA + c) = hi;
        }
    }
    __syncthreads();

    zacc(acc);
    wgemm<16>(aH0, aH1, bA, acc);  // final GEMM: A = t
#pragma unroll
    for (int i = 0; i < 2; ++i) {
        int r0 = base + mb + i * 16 + g;
#pragma unroll
        for (int j = 0; j < 4; ++j) {
            int c = nb + j * 8 + 2 * tg;
            if (r0 < NN) {
                *reinterpret_cast<float2*>(out + (size_t)r0 * HID + c) =
                    make_float2(acc[i][j][0] + sB2[c], acc[i][j][1] + sB2[c + 1]);
            }
            if (r0 + 8 < NN) {
                *reinterpret_cast<float2*>(out + (size_t)(r0 + 8) * HID + c) =
                    make_float2(acc[i][j][2] + sB2[c], acc[i][j][3] + sB2[c + 1]);
            }
        }
    }
}

// ---------------------------------------------------------------------------
extern "C" void kernel_launch(void* const* d_in, const int* in_sizes, int n_in,
                              void* d_out, int out_size) {
    const float* node_feats = (const float*)d_in[0];
    const int*   edge_idx   = (const int*)d_in[1];
    const float* edge_feats = (const float*)d_in[2];
    const float* node_W     = (const float*)d_in[3];
    const float* node_b     = (const float*)d_in[4];
    const float* edge_W     = (const float*)d_in[5];
    const float* edge_b     = (const float*)d_in[6];
    const float* msg_W1     = (const float*)d_in[7];
    const float* msg_b1     = (const float*)d_in[8];
    const float* msg_W2     = (const float*)d_in[9];
    const float* msg_b2     = (const float*)d_in[10];
    const float* upd_W1     = (const float*)d_in[11];
    const float* upd_b1     = (const float*)d_in[12];
    const float* upd_W2     = (const float*)d_in[13];
    const float* upd_b2     = (const float*)d_in[14];
    float* out = (float*)d_out;

    const int SMEM_NODE = (2 * 128 * LDA + 128) * 4;
    const int SMEM_UPD  = (3 * 128 * LDA + 2 * 128) * 4;

    cudaFuncSetAttribute(k_node,   cudaFuncAttributeMaxDynamicSharedMemorySize, SMEM_NODE);
    cudaFuncSetAttribute(k_edge,   cudaFuncAttributeMaxDynamicSharedMemorySize, EDGE_SMEM);
    cudaFuncSetAttribute(k_update, cudaFuncAttributeMaxDynamicSharedMemorySize, SMEM_UPD);

    const int NB_NODE = (NN + 127) / 128;  // 391
    const int NB_EDGE = NE / 128;          // 6250

    k_tW<<<128, 256>>>(node_W, edge_W, msg_W1, msg_W2, upd_W1, upd_W2);
    k_zero_agg<<<NN * HID / 4 / 256, 256>>>();
    k_node<<<NB_NODE, 512, SMEM_NODE>>>(node_feats, node_b);
    k_edge<<<NB_EDGE, 512, EDGE_SMEM>>>(edge_idx, edge_feats, edge_b, msg_b1, msg_b2);
    k_update<<<NB_NODE, 512, SMEM_UPD>>>(node_feats, upd_b1, upd_b2, out);
}

// round 9
// speedup vs baseline: 7.8936x; 1.5123x over previous
#include <cuda_runtime.h>
#include <cuda_fp16.h>
#include <cstdint>

#define HID 128
#define NN 50000
#define NE 800000
// byte strides (both ≡16 mod 128 -> ldmatrix conflict-free)
#define SA_STR 272   // A tiles: 136 halves/row
#define SB_STR 144   // B K=64 chunk buffers: 72 halves/row

extern __shared__ char dyn_smem[];

// ---------------- device scratch (allocation-free rule) ----------------
__device__ __half g_h[(size_t)NN * HID];   // node embeddings (fp16)
__device__ float  g_agg[(size_t)NN * HID]; // segment-sum accumulator (fp32)
__device__ __half g_nWt[128 * 128];        // node_W^T  [N][K] fp16
__device__ __half g_eWt[128 * 64];         // edge_W^T
__device__ __half g_W1t[128 * 256];        // msg_W1^T
__device__ __half g_W2t[128 * 128];        // msg_W2^T
__device__ __half g_U1t[128 * 256];        // upd_W1^T
__device__ __half g_U2t[128 * 128];        // upd_W2^T

// ======================= helpers (generic PTX) =========================
__device__ __forceinline__ uint32_t smem_u32(const void* p) {
    uint32_t a;
    asm("{ .reg .u64 t; cvta.to.shared.u64 t, %1; cvt.u32.u64 %0, t; }"
        : "=r"(a) : "l"(p));
    return a;
}
__device__ __forceinline__ void ldsm4(uint32_t r[4], uint32_t addr) {
    asm volatile("ldmatrix.sync.aligned.m8n8.x4.shared.b16 {%0,%1,%2,%3}, [%4];"
                 : "=r"(r[0]), "=r"(r[1]), "=r"(r[2]), "=r"(r[3]) : "r"(addr));
}
__device__ __forceinline__ void mma16(float c[4], const uint32_t a[4],
                                      uint32_t b0, uint32_t b1) {
    asm volatile("mma.sync.aligned.m16n8k16.row.col.f32.f16.f16.f32 "
                 "{%0,%1,%2,%3}, {%4,%5,%6,%7}, {%8,%9}, {%0,%1,%2,%3};"
                 : "+f"(c[0]), "+f"(c[1]), "+f"(c[2]), "+f"(c[3])
                 : "r"(a[0]), "r"(a[1]), "r"(a[2]), "r"(a[3]), "r"(b0), "r"(b1));
}
#define CP16(dst, src) \
    asm volatile("cp.async.cg.shared.global [%0], [%1], 16;" :: "r"(dst), "l"(src))
#define CP_COMMIT() asm volatile("cp.async.commit_group;" ::: "memory")
#define CP_WAIT(n)  asm volatile("cp.async.wait_group %0;" :: "n"(n) : "memory")

__device__ __forceinline__ void zacc(float acc[2][4][4]) {
#pragma unroll
    for (int i = 0; i < 2; ++i)
#pragma unroll
        for (int j = 0; j < 4; ++j)
#pragma unroll
            for (int k = 0; k < 4; ++k) acc[i][j][k] = 0.f;
}

// Warp GEMM: 32x32 output tile, KSTEPS k-steps of 16 (32 bytes each).
template <int KSTEPS>
__device__ __forceinline__ void wgemm(uint32_t aA0, uint32_t aA1,
                                      const uint32_t bA[2], float acc[2][4][4]) {
#pragma unroll
    for (int ks = 0; ks < KSTEPS; ++ks) {
        uint32_t a0[4], a1[4];
        ldsm4(a0, aA0 + ks * 32);
        ldsm4(a1, aA1 + ks * 32);
#pragma unroll
        for (int jj = 0; jj < 2; ++jj) {
            uint32_t b[4];
            ldsm4(b, bA[jj] + ks * 32);
            mma16(acc[0][2 * jj],     a0, b[0], b[1]);
            mma16(acc[0][2 * jj + 1], a0, b[2], b[3]);
            mma16(acc[1][2 * jj],     a1, b[0], b[1]);
            mma16(acc[1][2 * jj + 1], a1, b[2], b[3]);
        }
    }
}

__device__ __forceinline__ uint32_t a_off(int lane, int strideB) {
    int row = (lane & 7) + ((lane & 8) ? 8 : 0);
    return (uint32_t)row * strideB + ((lane & 16) ? 16 : 0);
}
__device__ __forceinline__ uint32_t b_off(int lane, int strideB) {
    int row = (lane & 7) + ((lane & 16) ? 8 : 0);
    return (uint32_t)row * strideB + ((lane & 8) ? 16 : 0);
}

// cp.async a [128n x 64k] fp16 weight chunk (row stride srcK halves)
__device__ __forceinline__ void stage_chunk(uint32_t dstB, const __half* srcBase,
                                            int srcK, int tid) {
#pragma unroll
    for (int i = tid; i < 128 * 8; i += 512) {
        int n = i >> 3, k8 = (i & 7) * 8;  // 8 halves = 16B segment
        CP16(dstB + (uint32_t)(n * SB_STR + k8 * 2),
             srcBase + (size_t)n * srcK + k8);
    }
}

// ---------------------------------------------------------------------------
// Prep: transpose + fp16-convert all weight matrices
// ---------------------------------------------------------------------------
__global__ void k_tW(const float* __restrict__ nW, const float* __restrict__ eW,
                     const float* __restrict__ W1, const float* __restrict__ W2,
                     const float* __restrict__ U1, const float* __restrict__ U2) {
    int t = blockIdx.x * blockDim.x + threadIdx.x;
    int tot = gridDim.x * blockDim.x;
    for (int i = t; i < 128 * 128; i += tot) {
        int n = i >> 7, k = i & 127;
        g_nWt[i] = __float2half_rn(nW[k * 128 + n]);
        g_W2t[i] = __float2half_rn(W2[k * 128 + n]);
        g_U2t[i] = __float2half_rn(U2[k * 128 + n]);
    }
    for (int i = t; i < 128 * 64; i += tot) {
        int n = i >> 6, k = i & 63;
        g_eWt[i] = __float2half_rn(eW[k * 128 + n]);
    }
    for (int i = t; i < 128 * 256; i += tot) {
        int n = i >> 8, k = i & 255;
        g_W1t[i] = __float2half_rn(W1[k * 128 + n]);
        g_U1t[i] = __float2half_rn(U1[k * 128 + n]);
    }
}

__global__ __launch_bounds__(256) void k_zero_agg() {
    size_t i = (size_t)blockIdx.x * 256 + threadIdx.x;
    reinterpret_cast<float4*>(g_agg)[i] = make_float4(0.f, 0.f, 0.f, 0.f);
}

// ---------------------------------------------------------------------------
// Kernel 1: h = fp16(node_feats @ node_W + node_b) -> g_h  (128 rows/block)
// smem: sA [128 x 272B] | sB [128 x 272B] | bias
// ---------------------------------------------------------------------------
static constexpr int NODE_SA = 0;
static constexpr int NODE_SB = 128 * SA_STR;          // 34816
static constexpr int NODE_BIAS = NODE_SB + 128 * SA_STR;
static constexpr int NODE_SMEM = NODE_BIAS + 512;

__global__ __launch_bounds__(512, 1) void k_node(const float* __restrict__ nf,
                                                 const float* __restrict__ b) {
    char* smem = dyn_smem;
    float* sBias = reinterpret_cast<float*>(smem + NODE_BIAS);
    const uint32_t sb0 = smem_u32(smem);
    const int tid = threadIdx.x, lane = tid & 31, w = tid >> 5;
    const int base = blockIdx.x * 128;

    if (tid < 128) sBias[tid] = b[tid];
    // A: nf fp32 -> fp16
    for (int i = tid; i < 128 * 32; i += 512) {
        int r = i >> 5, c = (i & 31) * 4;
        int gr = base + r;
        float4 v = make_float4(0.f, 0.f, 0.f, 0.f);
        if (gr < NN) v = *reinterpret_cast<const float4*>(nf + (size_t)gr * HID + c);
        __half2* p = reinterpret_cast<__half2*>(smem + NODE_SA + r * SA_STR + c * 2);
        p[0] = __floats2half2_rn(v.x, v.y);
        p[1] = __floats2half2_rn(v.z, v.w);
    }
    // B: g_nWt copy (16B segs)
    for (int i = tid; i < 128 * 16; i += 512) {
        int r = i >> 4, s = (i & 15);
        *reinterpret_cast<float4*>(smem + NODE_SB + r * SA_STR + s * 16) =
            *reinterpret_cast<const float4*>(
                reinterpret_cast<const char*>(g_nWt) + (size_t)r * 256 + s * 16);
    }
    __syncthreads();

    const int mb = (w & 3) * 32, nb = (w >> 2) * 32;
    uint32_t aA0 = sb0 + NODE_SA + (uint32_t)mb * SA_STR + a_off(lane, SA_STR);
    uint32_t aA1 = aA0 + 16 * SA_STR;
    uint32_t bA[2];
#pragma unroll
    for (int jj = 0; jj < 2; ++jj)
        bA[jj] = sb0 + NODE_SB + (uint32_t)(nb + jj * 16) * SA_STR + b_off(lane, SA_STR);

    float acc[2][4][4];
    zacc(acc);
    wgemm<8>(aA0, aA1, bA, acc);  // K = 128

    const int g = lane >> 2, tg = lane & 3;
#pragma unroll
    for (int i = 0; i < 2; ++i) {
        int r0 = base + mb + i * 16 + g;
#pragma unroll
        for (int j = 0; j < 4; ++j) {
            int c = nb + j * 8 + 2 * tg;
            if (r0 < NN)
                *reinterpret_cast<__half2*>(g_h + (size_t)r0 * HID + c) =
                    __floats2half2_rn(acc[i][j][0] + sBias[c], acc[i][j][1] + sBias[c + 1]);
            if (r0 + 8 < NN)
                *reinterpret_cast<__half2*>(g_h + (size_t)(r0 + 8) * HID + c) =
                    __floats2half2_rn(acc[i][j][2] + sBias[c], acc[i][j][3] + sBias[c + 1]);
        }
    }
}

// ---------------------------------------------------------------------------
// Kernel 2: fused edge pipeline, fp16, cp.async-streamed K=64 weight chunks.
// smem: sH [128x272B] | sE [128x272B] | B0 [128x144B] | B1 | biases | dst
// ---------------------------------------------------------------------------
static constexpr int SH_B  = 0;
static constexpr int SE_B  = 128 * SA_STR;             // 34816
static constexpr int B0_B  = SE_B * 2;                 // 69632
static constexpr int B1_B  = B0_B + 128 * SB_STR;      // 88064
static constexpr int MISC_B = B1_B + 128 * SB_STR;     // 106496
static constexpr int EDGE_SMEM = MISC_B + 4 * 128 * 4; // 108544

__global__ __launch_bounds__(512, 1) void k_edge(const int* __restrict__ eidx,
                                                 const float* __restrict__ ef,
                                                 const float* __restrict__ eb,
                                                 const float* __restrict__ b1,
                                                 const float* __restrict__ b2) {
    char* smem = dyn_smem;
    float* sEB = reinterpret_cast<float*>(smem + MISC_B);
    float* sB1b = sEB + 128;
    float* sB2b = sB1b + 128;
    int* sDst = reinterpret_cast<int*>(sB2b + 128);
    const uint32_t sb0 = smem_u32(smem);

    const int tid = threadIdx.x, lane = tid & 31, w = tid >> 5;
    const int e0 = blockIdx.x * 128;

    if (tid < 128) {
        sDst[tid] = eidx[NE + e0 + tid];
        sEB[tid] = eb[tid];
    } else if (tid < 256) {
        sB1b[tid - 128] = b1[tid - 128];
        sB2b[tid - 128] = b2[tid - 128];
    }

    // group0: c0 = eWt -> B0
    stage_chunk(sb0 + B0_B, g_eWt, 64, tid);
    CP_COMMIT();
    // group1: gather h[src] (fp16) -> sH   (16 x 16B segs per 128-half row)
#pragma unroll
    for (int i = tid; i < 128 * 16; i += 512) {
        int r = i >> 4, s = i & 15;
        int src = eidx[e0 + r];
        CP16(sb0 + SH_B + (uint32_t)(r * SA_STR + s * 16),
             g_h + (size_t)src * HID + s * 8);
    }
    CP_COMMIT();
    // group2: c1 = W1t[:,0:64] -> B1
    stage_chunk(sb0 + B1_B, g_W1t, 256, tid);
    CP_COMMIT();

    // ef [128x64] fp32 -> fp16 into sE cols 0..63
#pragma unroll
    for (int i = tid; i < 128 * 16; i += 512) {
        int r = i >> 4, c = (i & 15) * 4;
        float4 v = *reinterpret_cast<const float4*>(ef + (size_t)(e0 + r) * 64 + c);
        __half2* p = reinterpret_cast<__half2*>(smem + SE_B + r * SA_STR + c * 2);
        p[0] = __floats2half2_rn(v.x, v.y);
        p[1] = __floats2half2_rn(v.z, v.w);
    }

    const int mb = (w & 3) * 32, nb = (w >> 2) * 32;
    uint32_t aH0 = sb0 + SH_B + (uint32_t)mb * SA_STR + a_off(lane, SA_STR);
    uint32_t aH1 = aH0 + 16 * SA_STR;
    uint32_t aE0 = sb0 + SE_B + (uint32_t)mb * SA_STR + a_off(lane, SA_STR);
    uint32_t aE1 = aE0 + 16 * SA_STR;
    uint32_t b0A[2], b1A[2];
#pragma unroll
    for (int jj = 0; jj < 2; ++jj) {
        uint32_t off = (uint32_t)(nb + jj * 16) * SB_STR + b_off(lane, SB_STR);
        b0A[jj] = sb0 + B0_B + off;
        b1A[jj] = sb0 + B1_B + off;
    }

    const int g = lane >> 2, tg = lane & 3;
    float acc[2][4][4];

    // ---- GEMM0: e = ef @ eWt (K=64, c0 in B0) ----
    CP_WAIT(2);          // c0 complete (own copies)
    __syncthreads();     // publish c0 + ef + biases
    zacc(acc);
    wgemm<4>(aE0, aE1, b0A, acc);

    CP_WAIT(0);          // gather + c1 complete
    __syncthreads();     // publish sH, c1; B0 + sE(ef) free
    stage_chunk(sb0 + B0_B, g_W1t + 64, 256, tid);  // prefetch c2 -> B0
    CP_COMMIT();

    // epilogue0: e = acc + eb -> sE (fp16, full 128 cols)
#pragma unroll
    for (int i = 0; i < 2; ++i) {
        int r0 = mb + i * 16 + g;
#pragma unroll
        for (int j = 0; j < 4; ++j) {
            int c = nb + j * 8 + 2 * tg;
            *reinterpret_cast<__half2*>(smem + SE_B + r0 * SA_STR + c * 2) =
                __floats2half2_rn(acc[i][j][0] + sEB[c], acc[i][j][1] + sEB[c + 1]);
            *reinterpret_cast<__half2*>(smem + SE_B + (r0 + 8) * SA_STR + c * 2) =
                __floats2half2_rn(acc[i][j][2] + sEB[c], acc[i][j][3] + sEB[c + 1]);
        }
    }

    // ---- GEMM1: t = relu([h|e] @ W1t + b1), 4 K=64 chunks ----
    zacc(acc);
    wgemm<4>(aH0, aH1, b1A, acc);                 // c1: h k0:64
    CP_WAIT(0);
    __syncthreads();                              // publish c2 + epilogue0; B1 free
    stage_chunk(sb0 + B1_B, g_W1t + 128, 256, tid);  // prefetch c3 -> B1
    CP_COMMIT();
    wgemm<4>(aH0 + 128, aH1 + 128, b0A, acc);     // c2: h k64:128
    CP_WAIT(0);
    __syncthreads();                              // publish c3; B0 free
    stage_chunk(sb0 + B0_B, g_W1t + 192, 256, tid);  // prefetch c4 -> B0
    CP_COMMIT();
    wgemm<4>(aE0, aE1, b1A, acc);                 // c3: e k0:64
    CP_WAIT(0);
    __syncthreads();                              // publish c4; B1 free
    stage_chunk(sb0 + B1_B, g_W2t, 128, tid);     // prefetch c5 -> B1
    CP_COMMIT();
    wgemm<4>(aE0 + 128, aE1 + 128, b0A, acc);     // c4: e k64:128
    CP_WAIT(0);
    __syncthreads();                              // publish c5; B0 free
    stage_chunk(sb0 + B0_B, g_W2t + 64, 128, tid);  // prefetch c6 -> B0
    CP_COMMIT();

    // epilogue1: t = relu(acc + b1) -> sH (fp16; sH reads finished at c2)
#pragma unroll
    for (int i = 0; i < 2; ++i) {
        int r0 = mb + i * 16 + g;
#pragma unroll
        for (int j = 0; j < 4; ++j) {
            int c = nb + j * 8 + 2 * tg;
            *reinterpret_cast<__half2*>(smem + SH_B + r0 * SA_STR + c * 2) =
                __floats2half2_rn(fmaxf(acc[i][j][0] + sB1b[c], 0.f),
                                  fmaxf(acc[i][j][1] + sB1b[c + 1], 0.f));
            *reinterpret_cast<__half2*>(smem + SH_B + (r0 + 8) * SA_STR + c * 2) =
                __floats2half2_rn(fmaxf(acc[i][j][2] + sB1b[c], 0.f),
                                  fmaxf(acc[i][j][3] + sB1b[c + 1], 0.f));
        }
    }
    __syncthreads();                              // publish t (c5 already in)

    // ---- GEMM2: m = t @ W2t + b2 (K=128) ----
    zacc(acc);
    wgemm<4>(aH0, aH1, b1A, acc);                 // c5: t k0:64
    CP_WAIT(0);
    __syncthreads();                              // publish c6
    wgemm<4>(aH0 + 128, aH1 + 128, b0A, acc);     // c6: t k64:128

    // scatter-add into g_agg[dst]
#pragma unroll
    for (int i = 0; i < 2; ++i) {
        int r0 = mb + i * 16 + g;
        float* p0 = g_agg + (size_t)sDst[r0] * HID;
        float* p1 = g_agg + (size_t)sDst[r0 + 8] * HID;
#pragma unroll
        for (int j = 0; j < 4; ++j) {
            int c = nb + j * 8 + 2 * tg;
            atomicAdd(p0 + c, acc[i][j][0] + sB2b[c]);
            atomicAdd(p0 + c + 1, acc[i][j][1] + sB2b[c + 1]);
            atomicAdd(p1 + c, acc[i][j][2] + sB2b[c]);
            atomicAdd(p1 + c + 1, acc[i][j][3] + sB2b[c + 1]);
        }
    }
}

// ---------------------------------------------------------------------------
// Kernel 3: out = relu([nf|agg] @ U1 + ub1) @ U2 + ub2   (fp16 MMA, fp32 out)
// smem: sH | sE | sB (all 128x272B) | b1 | b2
// ---------------------------------------------------------------------------
static constexpr int UPD_SH = 0;
static constexpr int UPD_SE = 128 * SA_STR;
static constexpr int UPD_SB = 2 * 128 * SA_STR;
static constexpr int UPD_B1 = 3 * 128 * SA_STR;
static constexpr int UPD_B2 = UPD_B1 + 512;
static constexpr int UPD_SMEM = UPD_B2 + 512;

__global__ __launch_bounds__(512, 1) void k_update(const float* __restrict__ nf,
                                                   const float* __restrict__ b1,
                                                   const float* __restrict__ b2,
                                                   float* __restrict__ out) {
    char* smem = dyn_smem;
    float* sB1 = reinterpret_cast<float*>(smem + UPD_B1);
    float* sB2 = reinterpret_cast<float*>(smem + UPD_B2);
    const uint32_t sb0 = smem_u32(smem);

    const int tid = threadIdx.x, lane = tid & 31, w = tid >> 5;
    const int base = blockIdx.x * 128;

    if (tid < 128) {
        sB1[tid] = b1[tid];
        sB2[tid] = b2[tid];
    }
    // A tiles: nf -> sH, agg -> sE (fp32 -> fp16)
    for (int i = tid; i < 128 * 32; i += 512) {
        int r = i >> 5, c = (i & 31) * 4;
        int gr = base + r;
        float4 v0 = make_float4(0.f, 0.f, 0.f, 0.f), v1 = v0;
        if (gr < NN) {
            v0 = *reinterpret_cast<const float4*>(nf + (size_t)gr * HID + c);
            v1 = *reinterpret_cast<const float4*>(g_agg + (size_t)gr * HID + c);
        }
        __half2* p0 = reinterpret_cast<__half2*>(smem + UPD_SH + r * SA_STR + c * 2);
        p0[0] = __floats2half2_rn(v0.x, v0.y);
        p0[1] = __floats2half2_rn(v0.z, v0.w);
        __half2* p1 = reinterpret_cast<__half2*>(smem + UPD_SE + r * SA_STR + c * 2);
        p1[0] = __floats2half2_rn(v1.x, v1.y);
        p1[1] = __floats2half2_rn(v1.z, v1.w);
    }
    // B: U1t chunk0 (cols 0..127)
    for (int i = tid; i < 128 * 16; i += 512) {
        int r = i >> 4, s = (i & 15);
        *reinterpret_cast<float4*>(smem + UPD_SB + r * SA_STR + s * 16) =
            *reinterpret_cast<const float4*>(
                reinterpret_cast<const char*>(g_U1t) + (size_t)r * 512 + s * 16);
    }
    __syncthreads();

    const int mb = (w & 3) * 32, nb = (w >> 2) * 32;
    uint32_t aH0 = sb0 + UPD_SH + (uint32_t)mb * SA_STR + a_off(lane, SA_STR);
    uint32_t aH1 = aH0 + 16 * SA_STR;
    uint32_t aE0 = sb0 + UPD_SE + (uint32_t)mb * SA_STR + a_off(lane, SA_STR);
    uint32_t aE1 = aE0 + 16 * SA_STR;
    uint32_t bA[2];
#pragma unroll
    for (int jj = 0; jj < 2; ++jj)
        bA[jj] = sb0 + UPD_SB + (uint32_t)(nb + jj * 16) * SA_STR + b_off(lane, SA_STR);

    const int g = lane >> 2, tg = lane & 3;
    float acc[2][4][4];

    zacc(acc);
    wgemm<8>(aH0, aH1, bA, acc);  // chunk0: A = nf (K=128)
    __syncthreads();
    for (int i = tid; i < 128 * 16; i += 512) {  // U1t chunk1 (cols 128..255)
        int r = i >> 4, s = (i & 15);
        *reinterpret_cast<float4*>(smem + UPD_SB + r * SA_STR + s * 16) =
            *reinterpret_cast<const float4*>(
                reinterpret_cast<const char*>(g_U1t) + (size_t)r * 512 + 256 + s * 16);
    }
    __syncthreads();
    wgemm<8>(aE0, aE1, bA, acc);  // chunk1: A = agg
    __syncthreads();
    for (int i = tid; i < 128 * 16; i += 512) {  // U2t
        int r = i >> 4, s = (i & 15);
        *reinterpret_cast<float4*>(smem + UPD_SB + r * SA_STR + s * 16) =
            *reinterpret_cast<const float4*>(
                reinterpret_cast<const char*>(g_U2t) + (size_t)r * 256 + s * 16);
    }
    // epilogue: t = relu(acc + b1) -> sH (fp16)
#pragma unroll
    for (int i = 0; i < 2; ++i) {
        int r0 = mb + i * 16 + g;
#pragma unroll
        for (int j = 0; j < 4; ++j) {
            int c = nb + j * 8 + 2 * tg;
            *reinterpret_cast<__half2*>(smem + UPD_SH + r0 * SA_STR + c * 2) =
                __floats2half2_rn(fmaxf(acc[i][j][0] + sB1[c], 0.f),
                                  fmaxf(acc[i][j][1] + sB1[c + 1], 0.f));
            *reinterpret_cast<__half2*>(smem + UPD_SH + (r0 + 8) * SA_STR + c * 2) =
                __floats2half2_rn(fmaxf(acc[i][j][2] + sB1[c], 0.f),
                                  fmaxf(acc[i][j][3] + sB1[c + 1], 0.f));
        }
    }
    __syncthreads();

    zacc(acc);
    wgemm<8>(aH0, aH1, bA, acc);  // final GEMM: A = t (K=128)
#pragma unroll
    for (int i = 0; i < 2; ++i) {
        int r0 = base + mb + i * 16 + g;
#pragma unroll
        for (int j = 0; j < 4; ++j) {
            int c = nb + j * 8 + 2 * tg;
            if (r0 < NN)
                *reinterpret_cast<float2*>(out + (size_t)r0 * HID + c) =
                    make_float2(acc[i][j][0] + sB2[c], acc[i][j][1] + sB2[c + 1]);
            if (r0 + 8 < NN)
                *reinterpret_cast<float2*>(out + (size_t)(r0 + 8) * HID + c) =
                    make_float2(acc[i][j][2] + sB2[c], acc[i][j][3] + sB2[c + 1]);
        }
    }
}

// ---------------------------------------------------------------------------
extern "C" void kernel_launch(void* const* d_in, const int* in_sizes, int n_in,
                              void* d_out, int out_size) {
    const float* node_feats = (const float*)d_in[0];
    const int*   edge_idx   = (const int*)d_in[1];
    const float* edge_feats = (const float*)d_in[2];
    const float* node_W     = (const float*)d_in[3];
    const float* node_b     = (const float*)d_in[4];
    const float* edge_W     = (const float*)d_in[5];
    const float* edge_b     = (const float*)d_in[6];
    const float* msg_W1     = (const float*)d_in[7];
    const float* msg_b1     = (const float*)d_in[8];
    const float* msg_W2     = (const float*)d_in[9];
    const float* msg_b2     = (const float*)d_in[10];
    const float* upd_W1     = (const float*)d_in[11];
    const float* upd_b1     = (const float*)d_in[12];
    const float* upd_W2     = (const float*)d_in[13];
    const float* upd_b2     = (const float*)d_in[14];
    float* out = (float*)d_out;

    cudaFuncSetAttribute(k_node,   cudaFuncAttributeMaxDynamicSharedMemorySize, NODE_SMEM);
    cudaFuncSetAttribute(k_edge,   cudaFuncAttributeMaxDynamicSharedMemorySize, EDGE_SMEM);
    cudaFuncSetAttribute(k_update, cudaFuncAttributeMaxDynamicSharedMemorySize, UPD_SMEM);

    const int NB_NODE = (NN + 127) / 128;  // 391
    const int NB_EDGE = NE / 128;          // 6250

    k_tW<<<128, 256>>>(node_W, edge_W, msg_W1, msg_W2, upd_W1, upd_W2);
    k_zero_agg<<<NN * HID / 4 / 256, 256>>>();
    k_node<<<NB_NODE, 512, NODE_SMEM>>>(node_feats, node_b);
    k_edge<<<NB_EDGE, 512, EDGE_SMEM>>>(edge_idx, edge_feats, edge_b, msg_b1, msg_b2);
    k_update<<<NB_NODE, 512, UPD_SMEM>>>(node_feats, upd_b1, upd_b2, out);
}